// round 14
// baseline (speedup 1.0000x reference)
#include <cuda_runtime.h>
#include <cuda_fp16.h>
#include <math.h>

#define NB   2
#define NS   2048
#define NHID 2048
#define NH   8
#define NKV  2
#define ND   256
#define NSW  512
#define NQKV 3072   // 2048 q + 512 k + 512 v

typedef unsigned long long u64;
typedef unsigned int u32;

__device__ __forceinline__ float2 ffma2(float2 c, float2 a, float2 b) {
    u64 uc = *reinterpret_cast<u64*>(&c);
    u64 ua = *reinterpret_cast<u64*>(&a);
    u64 ub = *reinterpret_cast<u64*>(&b);
    asm("fma.rn.f32x2 %0, %1, %2, %0;" : "+l"(uc) : "l"(ua), "l"(ub));
    float2 r;
    *reinterpret_cast<u64*>(&r) = uc;
    return r;
}

__device__ __forceinline__ u32 smem_u32(const void* p) {
    u32 a;
    asm("{ .reg .u64 t; cvta.to.shared.u64 t, %1; cvt.u32.u64 %0, t; }" : "=r"(a) : "l"(p));
    return a;
}

#define SWZ(o) ((o) ^ (((o) >> 3) & 0x70))

#define CP_ASYNC16(saddr, gptr) \
    asm volatile("cp.async.ca.shared.global [%0], [%1], 16;" :: "r"(saddr), "l"(gptr) : "memory")
#define CP_COMMIT() asm volatile("cp.async.commit_group;" ::: "memory")
#define CP_WAIT1()  asm volatile("cp.async.wait_group 1;" ::: "memory")
#define CP_WAIT0()  asm volatile("cp.async.wait_group 0;" ::: "memory")

#define LDMX4(r0, r1, r2, r3, addr) \
    asm volatile("ldmatrix.sync.aligned.m8n8.x4.shared.b16 {%0,%1,%2,%3}, [%4];" \
        : "=r"(r0), "=r"(r1), "=r"(r2), "=r"(r3) : "r"(addr))

#define MMAF16(d0, d1, d2, d3, a0, a1, a2, a3, b0, b1) \
    asm volatile("mma.sync.aligned.m16n8k16.row.col.f32.f16.f16.f32 " \
        "{%0,%1,%2,%3}, {%4,%5,%6,%7}, {%8,%9}, {%0,%1,%2,%3};" \
        : "+f"(d0), "+f"(d1), "+f"(d2), "+f"(d3) \
        : "r"(a0), "r"(a1), "r"(a2), "r"(a3), "r"(b0), "r"(b1))

// ---------------- scratch ----------------
__device__ float g_qkvp[(size_t)NB*NS*NQKV];
__device__ float g_Q  [(size_t)NB*NH*NS*ND];
__device__ float g_K  [(size_t)NB*NKV*NS*ND];
__device__ float g_V  [(size_t)NB*NKV*NS*ND];
__device__ float g_bs [(size_t)NB*NKV*(NS/64)*ND];
__device__ float g_invf[128];

__device__ __half g_ah[(size_t)NB*NS*NHID], g_al[(size_t)NB*NS*NHID];
__device__ __half g_wqkv[(size_t)NQKV*NHID];
__device__ __half g_wo[(size_t)NHID*NHID];
__device__ __half g_oh[(size_t)NB*NS*NHID];

// ---------------- rope inv-freq table (fp64 once) ----------------
__global__ void invf_init_kernel(float* tab) {
    int j = threadIdx.x;
    tab[j] = (float)exp2(-(double)j * 0.15571537944784511);  // log2(1e6)/128
}

// ---------------- fp32 -> fp16 hi/lo split ----------------
__global__ __launch_bounds__(256) void cvt_split_h(
    const float* __restrict__ x, __half* __restrict__ hi,
    __half* __restrict__ lo, int n4)
{
    int i = blockIdx.x * 256 + threadIdx.x;
    if (i >= n4) return;
    float4 v = *(const float4*)(x + (size_t)i * 4);
    __half h0 = __float2half(v.x), h1 = __float2half(v.y);
    __half h2 = __float2half(v.z), h3 = __float2half(v.w);
    __half l0 = __float2half(v.x - __half2float(h0));
    __half l1 = __float2half(v.y - __half2float(h1));
    __half l2 = __float2half(v.z - __half2float(h2));
    __half l3 = __float2half(v.w - __half2float(h3));
    ushort4 H, L;
    H.x = __half_as_ushort(h0); H.y = __half_as_ushort(h1);
    H.z = __half_as_ushort(h2); H.w = __half_as_ushort(h3);
    L.x = __half_as_ushort(l0); L.y = __half_as_ushort(l1);
    L.z = __half_as_ushort(l2); L.w = __half_as_ushort(l3);
    *(ushort4*)(hi + (size_t)i * 4) = H;
    *(ushort4*)(lo + (size_t)i * 4) = L;
}

// ---------------- fp32 -> fp16 ----------------
__global__ __launch_bounds__(256) void cvt_h(
    const float* __restrict__ x, __half* __restrict__ y, int n4)
{
    int i = blockIdx.x * 256 + threadIdx.x;
    if (i >= n4) return;
    float4 v = *(const float4*)(x + (size_t)i * 4);
    ushort4 H;
    H.x = __half_as_ushort(__float2half(v.x));
    H.y = __half_as_ushort(__float2half(v.y));
    H.z = __half_as_ushort(__float2half(v.z));
    H.w = __half_as_ushort(__float2half(v.w));
    *(ushort4*)(y + (size_t)i * 4) = H;
}

// ====== range-conditional split GEMM: lo-term only for loLo <= bn < loHi =====
#define GS_STAGE 49152
#define GS_AH 0
#define GS_AL 16384
#define GS_B  32768
#define GS_TOTAL (2 * GS_STAGE)

__global__ __launch_bounds__(512, 2) void gemm_mma2(
    const __half* __restrict__ Ah, const __half* __restrict__ Al,
    const __half* __restrict__ B,
    float* __restrict__ C, int M, int ldc, int K, int loLo, int loHi)
{
    extern __shared__ char sm[];
    u32 sb = smem_u32(sm);
    int tid = threadIdx.x;
    int lane = tid & 31, wid = tid >> 5;
    int warpM = wid & 3, warpN = wid >> 2;
    int bm = blockIdx.y * 128, bn = blockIdx.x * 128;
    const bool useLo = (bn >= loLo) && (bn < loHi);

    const int nIt = K >> 6;

    float d[2][4][4];
#pragma unroll
    for (int i = 0; i < 2; i++)
#pragma unroll
        for (int j = 0; j < 4; j++)
#pragma unroll
            for (int c = 0; c < 4; c++) d[i][j][c] = 0.f;

    int lr = tid >> 3, lcb = tid & 7;
    u32 ldo = SWZ((u32)(lr * 128 + lcb * 16));
    size_t gA = (size_t)(bm + lr) * K + lcb * 8;
    size_t gB = (size_t)(bn + lr) * K + lcb * 8;
    size_t rowK64 = (size_t)64 * K;

#pragma unroll
    for (int pit = 0; pit < 2; pit++) {
        u32 stg = sb + pit * GS_STAGE;
        int k0 = pit << 6;
        CP_ASYNC16(stg + GS_AH + ldo,        Ah + gA + k0);
        CP_ASYNC16(stg + GS_AH + ldo + 8192, Ah + gA + rowK64 + k0);
        if (useLo) {
            CP_ASYNC16(stg + GS_AL + ldo,        Al + gA + k0);
            CP_ASYNC16(stg + GS_AL + ldo + 8192, Al + gA + rowK64 + k0);
        }
        CP_ASYNC16(stg + GS_B  + ldo,        B  + gB + k0);
        CP_ASYNC16(stg + GS_B  + ldo + 8192, B  + gB + rowK64 + k0);
        CP_COMMIT();
    }

    u32 arowb[2], axm[2];
#pragma unroll
    for (int i = 0; i < 2; i++) {
        int row = warpM * 32 + i * 16 + (lane & 15);
        arowb[i] = (u32)(row * 128);
        axm[i] = (u32)((row & 7) << 4);
    }
    u32 browb[2], bxm[2];
#pragma unroll
    for (int p = 0; p < 2; p++) {
        int row = warpN * 32 + p * 16 + (lane & 7) + ((lane >> 4) << 3);
        browb[p] = (u32)(row * 128);
        bxm[p] = (u32)((row & 7) << 4);
    }
    u32 colA_base = (u32)((lane >> 4) << 4);
    u32 colB_base = (u32)(((lane >> 3) & 1) << 4);

    for (int it = 0; it < nIt; it++) {
        CP_WAIT1();
        __syncthreads();
        u32 stgA = sb + (it & 1) * GS_STAGE;
#pragma unroll
        for (int kk = 0; kk < 4; kk++) {
            u32 colA = (u32)(kk * 32) + colA_base;
            u32 colB = (u32)(kk * 32) + colB_base;
            u32 ah[2][4], al[2][4], bb[2][4];
#pragma unroll
            for (int i = 0; i < 2; i++) {
                u32 off = arowb[i] + (colA ^ axm[i]);
                LDMX4(ah[i][0], ah[i][1], ah[i][2], ah[i][3], stgA + GS_AH + off);
                if (useLo)
                    LDMX4(al[i][0], al[i][1], al[i][2], al[i][3], stgA + GS_AL + off);
            }
#pragma unroll
            for (int p = 0; p < 2; p++)
                LDMX4(bb[p][0], bb[p][1], bb[p][2], bb[p][3],
                      stgA + GS_B + browb[p] + (colB ^ bxm[p]));
#pragma unroll
            for (int i = 0; i < 2; i++)
#pragma unroll
                for (int j = 0; j < 4; j++) {
                    int p = j >> 1, h2 = (j & 1) << 1;
                    MMAF16(d[i][j][0], d[i][j][1], d[i][j][2], d[i][j][3],
                           ah[i][0], ah[i][1], ah[i][2], ah[i][3],
                           bb[p][h2], bb[p][h2 + 1]);
                }
            if (useLo) {
#pragma unroll
                for (int i = 0; i < 2; i++)
#pragma unroll
                    for (int j = 0; j < 4; j++) {
                        int p = j >> 1, h2 = (j & 1) << 1;
                        MMAF16(d[i][j][0], d[i][j][1], d[i][j][2], d[i][j][3],
                               al[i][0], al[i][1], al[i][2], al[i][3],
                               bb[p][h2], bb[p][h2 + 1]);
                    }
            }
        }
        __syncthreads();
        if (it + 2 < nIt) {
            u32 stg = sb + (it & 1) * GS_STAGE;
            int k0 = (it + 2) << 6;
            CP_ASYNC16(stg + GS_AH + ldo,        Ah + gA + k0);
            CP_ASYNC16(stg + GS_AH + ldo + 8192, Ah + gA + rowK64 + k0);
            if (useLo) {
                CP_ASYNC16(stg + GS_AL + ldo,        Al + gA + k0);
                CP_ASYNC16(stg + GS_AL + ldo + 8192, Al + gA + rowK64 + k0);
            }
            CP_ASYNC16(stg + GS_B  + ldo,        B  + gB + k0);
            CP_ASYNC16(stg + GS_B  + ldo + 8192, B  + gB + rowK64 + k0);
        }
        CP_COMMIT();
    }
    CP_WAIT0();

#pragma unroll
    for (int i = 0; i < 2; i++) {
#pragma unroll
        for (int j = 0; j < 4; j++) {
            int r0 = bm + warpM * 32 + i * 16 + (lane >> 2);
            int cc = bn + warpN * 32 + j * 8 + (lane & 3) * 2;
            float2 v0 = make_float2(d[i][j][0], d[i][j][1]);
            float2 v1 = make_float2(d[i][j][2], d[i][j][3]);
            *(float2*)(C + (size_t)r0 * ldc + cc) = v0;
            *(float2*)(C + (size_t)(r0 + 8) * ldc + cc) = v1;
        }
    }
}

// ================= single-term GEMM (A*B, f32 accum) =================
#define G1_STAGE 32768
#define G1_A 0
#define G1_B 16384
#define G1_TOTAL (2 * G1_STAGE)

__global__ __launch_bounds__(512, 2) void gemm_mma1(
    const __half* __restrict__ A, const __half* __restrict__ B,
    float* __restrict__ C, int M, int ldc, int K)
{
    extern __shared__ char sm[];
    u32 sb = smem_u32(sm);
    int tid = threadIdx.x;
    int lane = tid & 31, wid = tid >> 5;
    int warpM = wid & 3, warpN = wid >> 2;
    int bm = blockIdx.y * 128, bn = blockIdx.x * 128;

    const int nIt = K >> 6;

    float d[2][4][4];
#pragma unroll
    for (int i = 0; i < 2; i++)
#pragma unroll
        for (int j = 0; j < 4; j++)
#pragma unroll
            for (int c = 0; c < 4; c++) d[i][j][c] = 0.f;

    int lr = tid >> 3, lcb = tid & 7;
    u32 ldo = SWZ((u32)(lr * 128 + lcb * 16));
    size_t gA = (size_t)(bm + lr) * K + lcb * 8;
    size_t gB = (size_t)(bn + lr) * K + lcb * 8;
    size_t rowK64 = (size_t)64 * K;

#pragma unroll
    for (int pit = 0; pit < 2; pit++) {
        u32 stg = sb + pit * G1_STAGE;
        int k0 = pit << 6;
        CP_ASYNC16(stg + G1_A + ldo,        A + gA + k0);
        CP_ASYNC16(stg + G1_A + ldo + 8192, A + gA + rowK64 + k0);
        CP_ASYNC16(stg + G1_B + ldo,        B + gB + k0);
        CP_ASYNC16(stg + G1_B + ldo + 8192, B + gB + rowK64 + k0);
        CP_COMMIT();
    }

    u32 arowb[2], axm[2];
#pragma unroll
    for (int i = 0; i < 2; i++) {
        int row = warpM * 32 + i * 16 + (lane & 15);
        arowb[i] = (u32)(row * 128);
        axm[i] = (u32)((row & 7) << 4);
    }
    u32 browb[2], bxm[2];
#pragma unroll
    for (int p = 0; p < 2; p++) {
        int row = warpN * 32 + p * 16 + (lane & 7) + ((lane >> 4) << 3);
        browb[p] = (u32)(row * 128);
        bxm[p] = (u32)((row & 7) << 4);
    }
    u32 colA_base = (u32)((lane >> 4) << 4);
    u32 colB_base = (u32)(((lane >> 3) & 1) << 4);

    for (int it = 0; it < nIt; it++) {
        CP_WAIT1();
        __syncthreads();
        u32 stgA = sb + (it & 1) * G1_STAGE;
#pragma unroll
        for (int kk = 0; kk < 4; kk++) {
            u32 colA = (u32)(kk * 32) + colA_base;
            u32 colB = (u32)(kk * 32) + colB_base;
            u32 aa[2][4], bb[2][4];
#pragma unroll
            for (int i = 0; i < 2; i++) {
                u32 off = arowb[i] + (colA ^ axm[i]);
                LDMX4(aa[i][0], aa[i][1], aa[i][2], aa[i][3], stgA + G1_A + off);
            }
#pragma unroll
            for (int p = 0; p < 2; p++)
                LDMX4(bb[p][0], bb[p][1], bb[p][2], bb[p][3],
                      stgA + G1_B + browb[p] + (colB ^ bxm[p]));
#pragma unroll
            for (int i = 0; i < 2; i++)
#pragma unroll
                for (int j = 0; j < 4; j++) {
                    int p = j >> 1, h2 = (j & 1) << 1;
                    MMAF16(d[i][j][0], d[i][j][1], d[i][j][2], d[i][j][3],
                           aa[i][0], aa[i][1], aa[i][2], aa[i][3],
                           bb[p][h2], bb[p][h2 + 1]);
                }
        }
        __syncthreads();
        if (it + 2 < nIt) {
            u32 stg = sb + (it & 1) * G1_STAGE;
            int k0 = (it + 2) << 6;
            CP_ASYNC16(stg + G1_A + ldo,        A + gA + k0);
            CP_ASYNC16(stg + G1_A + ldo + 8192, A + gA + rowK64 + k0);
            CP_ASYNC16(stg + G1_B + ldo,        B + gB + k0);
            CP_ASYNC16(stg + G1_B + ldo + 8192, B + gB + rowK64 + k0);
        }
        CP_COMMIT();
    }
    CP_WAIT0();

#pragma unroll
    for (int i = 0; i < 2; i++) {
#pragma unroll
        for (int j = 0; j < 4; j++) {
            int r0 = bm + warpM * 32 + i * 16 + (lane >> 2);
            int cc = bn + warpN * 32 + j * 8 + (lane & 3) * 2;
            float2 v0 = make_float2(d[i][j][0], d[i][j][1]);
            float2 v1 = make_float2(d[i][j][2], d[i][j][3]);
            *(float2*)(C + (size_t)r0 * ldc + cc) = v0;
            *(float2*)(C + (size_t)(r0 + 8) * ldc + cc) = v1;
        }
    }
}

// ---------------- fused RoPE + unit-LayerNorm (+ q scale) ----------------
__global__ __launch_bounds__(256) void rope_ln_kernel(
    const float* __restrict__ qkvp, const float* __restrict__ invf_tab,
    float* __restrict__ Qo, float* __restrict__ Ko, float* __restrict__ Vo)
{
    __shared__ float sh[ND];
    __shared__ float redA[8], redB[8];
    __shared__ float s_mu, s_inv;
    int bs = blockIdx.x;
    int s  = bs & (NS - 1);
    int b  = bs >> 11;
    int u  = blockIdx.y;
    int d  = threadIdx.x;

    const float* src; float* dst; bool doRope; float scale;
    if (u < NH) {
        src = qkvp + (size_t)bs * NQKV + u * ND;
        dst = Qo + (((size_t)(b * NH + u) * NS) + s) * ND;
        doRope = true; scale = 16.0f;
    } else if (u < NH + NKV) {
        int h = u - NH;
        src = qkvp + (size_t)bs * NQKV + 2048 + h * ND;
        dst = Ko + (((size_t)(b * NKV + h) * NS) + s) * ND;
        doRope = true; scale = 1.0f;
    } else {
        int h = u - NH - NKV;
        src = qkvp + (size_t)bs * NQKV + 2560 + h * ND;
        dst = Vo + (((size_t)(b * NKV + h) * NS) + s) * ND;
        doRope = false; scale = 1.0f;
    }

    float x = src[d];
    float r = x;
    if (doRope) {
        sh[d] = x;
        __syncthreads();
        int j = d & 127;
        float invf = invf_tab[j];
        float ang = (float)s * invf;
        float c = cosf(ang), sn = sinf(ang);
        float partner = (d < 128) ? -sh[d + 128] : sh[d - 128];
        r = x * c + partner * sn;
    }
    float s1 = r, s2 = r * r;
#pragma unroll
    for (int off = 16; off; off >>= 1) {
        s1 += __shfl_xor_sync(~0u, s1, off);
        s2 += __shfl_xor_sync(~0u, s2, off);
    }
    int w = d >> 5;
    if ((d & 31) == 0) { redA[w] = s1; redB[w] = s2; }
    __syncthreads();
    if (d == 0) {
        float A = 0.f, Bv = 0.f;
#pragma unroll
        for (int i = 0; i < 8; i++) { A += redA[i]; Bv += redB[i]; }
        float mu  = A * (1.0f / 256.0f);
        float var = Bv * (1.0f / 256.0f) - mu * mu;
        s_mu = mu; s_inv = rsqrtf(var + 1e-6f);
    }
    __syncthreads();
    dst[d] = (r - s_mu) * s_inv * scale;
}

// ---------------- 64-row block sums of V (mask-correction) ----------------
__global__ __launch_bounds__(256) void vblocksum_kernel(
    const float* __restrict__ V, float* __restrict__ BSo)
{
    int bh = blockIdx.x, blk = blockIdx.y, d = threadIdx.x;
    const float* v = V + ((size_t)bh * NS + blk * 64) * ND + d;
    float s = 0.f;
#pragma unroll 8
    for (int i = 0; i < 64; i++) s += v[(size_t)i * ND];
    BSo[((size_t)bh * (NS / 64) + blk) * ND + d] = s;
}

// ---------------- sliding-window softcapped flash attention ----------------
#define AT_BM 64
#define AT_BN 64
#define QS_STR 260
#define KT_STR 68
#define VS_STR 260
#define PS_STR 68
#define ATT_SMEM ((16640 + 17408 + 16640 + 4352 + 256) * 4)

__global__ __launch_bounds__(256, 1) void attn_kernel(
    const float* __restrict__ Q, const float* __restrict__ K,
    const float* __restrict__ V, const float* __restrict__ BS,
    __half* __restrict__ OH)
{
    extern __shared__ __align__(16) float smf[];
    float* Qs    = smf;
    float* Kt    = smf + 16640;
    float* Vs    = smf + 34048;
    float* Ps    = smf + 50688;
    float* corrv = smf + 55040;

    int tid = threadIdx.x;
    int tx = tid & 15, ty = tid >> 4;
    int qt = blockIdx.x, h = blockIdx.y, b = blockIdx.z;
    int qs = qt * AT_BM;
    int kvh = h >> 2;

    const float* Qb = Q + (((size_t)(b * NH  + h  ) * NS) + qs) * ND;
    const float* Kb = K + ((size_t)(b * NKV + kvh) * NS) * ND;
    const float* Vb = V + ((size_t)(b * NKV + kvh) * NS) * ND;
    const float* Bb = BS + (size_t)(b * NKV + kvh) * (NS / 64) * ND;

    int t0 = qs - (NSW - 1);
    int kstart = (t0 <= 0) ? 0 : (t0 & ~63);
    int kend = qs + AT_BM;
    float Ncf = (float)(NS - (kend - kstart));
    int bs0 = kstart >> 6, bs1 = kend >> 6;

    {
        float c = 0.f;
#pragma unroll
        for (int blk = 0; blk < NS / 64; blk++) {
            float x = Bb[(size_t)blk * ND + tid];
            if (blk < bs0 || blk >= bs1) c += x;
        }
        corrv[tid] = c;
    }
#pragma unroll
    for (int it = 0; it < 16; it++) {
        int idx = tid + it * 256;
        int row = idx >> 6, c4 = idx & 63;
        float4 qv = *(const float4*)(Qb + (size_t)row * ND + (c4 << 2));
        float* q = Qs + row * QS_STR + (c4 << 2);
        q[0] = qv.x; q[1] = qv.y; q[2] = qv.z; q[3] = qv.w;
    }

    float2 acc[4][8];
#pragma unroll
    for (int i = 0; i < 4; i++)
#pragma unroll
        for (int c = 0; c < 8; c++) acc[i][c] = make_float2(0.f, 0.f);
    float Mrow[4], Lrow[4];
#pragma unroll
    for (int i = 0; i < 4; i++) { Mrow[i] = -3.0e38f; Lrow[i] = 0.f; }

    for (int k0 = kstart; k0 < kend; k0 += AT_BN) {
        __syncthreads();
#pragma unroll
        for (int it = 0; it < 16; it++) {
            int idx = tid + it * 256;
            int row = idx >> 6, c4 = idx & 63;
            float4 kv = *(const float4*)(Kb + (size_t)(k0 + row) * ND + (c4 << 2));
            Kt[(c4 * 4 + 0) * KT_STR + row] = kv.x;
            Kt[(c4 * 4 + 1) * KT_STR + row] = kv.y;
            Kt[(c4 * 4 + 2) * KT_STR + row] = kv.z;
            Kt[(c4 * 4 + 3) * KT_STR + row] = kv.w;
            float4 vv = *(const float4*)(Vb + (size_t)(k0 + row) * ND + (c4 << 2));
            *(float4*)(Vs + row * VS_STR + (c4 << 2)) = vv;
        }
        __syncthreads();

        float2 s2[4][2];
#pragma unroll
        for (int i = 0; i < 4; i++) { s2[i][0] = make_float2(0.f,0.f); s2[i][1] = make_float2(0.f,0.f); }
        const float* qrow = Qs + (ty << 2) * QS_STR;
#pragma unroll 8
        for (int d = 0; d < ND; d++) {
            float4 kq  = *(const float4*)(Kt + d * KT_STR + (tx << 2));
            float2 b01 = make_float2(kq.x, kq.y);
            float2 b23 = make_float2(kq.z, kq.w);
#pragma unroll
            for (int ii = 0; ii < 4; ii++) {
                float a = qrow[ii * QS_STR + d];
                float2 ap = make_float2(a, a);
                s2[ii][0] = ffma2(s2[ii][0], ap, b01);
                s2[ii][1] = ffma2(s2[ii][1], ap, b23);
            }
        }

#pragma unroll
        for (int ii = 0; ii < 4; ii++) {
            int gi = qs + (ty << 2) + ii;
            float sc[4] = { s2[ii][0].x, s2[ii][0].y, s2[ii][1].x, s2[ii][1].y };
            float rmax = -1e30f;
#pragma unroll
            for (int jj = 0; jj < 4; jj++) {
                int gj = k0 + (tx << 2) + jj;
                float v;
                if (gj <= gi && gj > gi - NSW)
                    v = 30.0f * tanhf(sc[jj] * (1.0f / 30.0f));
                else
                    v = -30.0f;
                sc[jj] = v;
                rmax = fmaxf(rmax, v);
            }
#pragma unroll
            for (int off = 8; off; off >>= 1) rmax = fmaxf(rmax, __shfl_xor_sync(~0u, rmax, off));
            float Mnew = fmaxf(Mrow[ii], rmax);
            float f = expf(Mrow[ii] - Mnew);
            Mrow[ii] = Mnew;
            float rs = 0.f;
#pragma unroll
            for (int jj = 0; jj < 4; jj++) {
                float p = expf(sc[jj] - Mnew);
                Ps[((ty << 2) + ii) * PS_STR + (tx << 2) + jj] = p;
                rs += p;
            }
#pragma unroll
            for (int off = 8; off; off >>= 1) rs += __shfl_xor_sync(~0u, rs, off);
            Lrow[ii] = Lrow[ii] * f + rs;
#pragma unroll
            for (int cc = 0; cc < 8; cc++) { acc[ii][cc].x *= f; acc[ii][cc].y *= f; }
        }
        __syncthreads();

#pragma unroll 4
        for (int kk = 0; kk < AT_BN; kk++) {
            const float* vrow = Vs + kk * VS_STR + (tx << 4);
            float4 v0 = *(const float4*)(vrow);
            float4 v1 = *(const float4*)(vrow + 4);
            float4 v2 = *(const float4*)(vrow + 8);
            float4 v3 = *(const float4*)(vrow + 12);
            float2 vv[8] = {
                make_float2(v0.x,v0.y), make_float2(v0.z,v0.w),
                make_float2(v1.x,v1.y), make_float2(v1.z,v1.w),
                make_float2(v2.x,v2.y), make_float2(v2.z,v2.w),
                make_float2(v3.x,v3.y), make_float2(v3.z,v3.w)
            };
#pragma unroll
            for (int ii = 0; ii < 4; ii++) {
                float p = Ps[((ty << 2) + ii) * PS_STR + kk];
                float2 pp = make_float2(p, p);
#pragma unroll
                for (int cc = 0; cc < 8; cc++) acc[ii][cc] = ffma2(acc[ii][cc], pp, vv[cc]);
            }
        }
    }

    // epilogue: exact masked correction, normalize, write fp16
#pragma unroll
    for (int ii = 0; ii < 4; ii++) {
        float ce = expf(-30.0f - Mrow[ii]);
        float invL = 1.0f / (Lrow[ii] + ce * Ncf);
        int row = qs + (ty << 2) + ii;
        size_t obase = ((size_t)(b * NS + row) * NHID) + h * ND + (tx << 4);
#pragma unroll
        for (int g = 0; g < 4; g++) {
            float2 a0 = acc[ii][g * 2], a1 = acc[ii][g * 2 + 1];
            int c0 = (tx << 4) + g * 4;
            float o0 = (a0.x + ce * corrv[c0 + 0]) * invL;
            float o1 = (a0.y + ce * corrv[c0 + 1]) * invL;
            float o2 = (a1.x + ce * corrv[c0 + 2]) * invL;
            float o3 = (a1.y + ce * corrv[c0 + 3]) * invL;
            ushort4 H;
            H.x = __half_as_ushort(__float2half(o0));
            H.y = __half_as_ushort(__float2half(o1));
            H.z = __half_as_ushort(__float2half(o2));
            H.w = __half_as_ushort(__float2half(o3));
            *(ushort4*)(OH + obase + g * 4) = H;
        }
    }
}

// ---------------- launch ----------------
extern "C" void kernel_launch(void* const* d_in, const int* in_sizes, int n_in,
                              void* d_out, int out_size)
{
    const float* hs = (const float*)d_in[0];
    const float* Wq = (const float*)d_in[1];
    const float* Wk = (const float*)d_in[2];
    const float* Wv = (const float*)d_in[3];
    const float* Wo = (const float*)d_in[4];
    float* out = (float*)d_out;

    float *qkvp, *Qn, *Kn, *Vn, *bs, *invf;
    cudaGetSymbolAddress((void**)&qkvp, g_qkvp);
    cudaGetSymbolAddress((void**)&Qn,  g_Q);
    cudaGetSymbolAddress((void**)&Kn,  g_K);
    cudaGetSymbolAddress((void**)&Vn,  g_V);
    cudaGetSymbolAddress((void**)&bs,  g_bs);
    cudaGetSymbolAddress((void**)&invf, g_invf);

    __half *ah,*al,*wqkv,*wo,*oh;
    cudaGetSymbolAddress((void**)&ah, g_ah); cudaGetSymbolAddress((void**)&al, g_al);
    cudaGetSymbolAddress((void**)&wqkv, g_wqkv);
    cudaGetSymbolAddress((void**)&wo, g_wo);
    cudaGetSymbolAddress((void**)&oh, g_oh);

    const int M = NB * NS;   // 4096

    cudaFuncSetAttribute(gemm_mma2, cudaFuncAttributeMaxDynamicSharedMemorySize, GS_TOTAL);
    cudaFuncSetAttribute(gemm_mma1, cudaFuncAttributeMaxDynamicSharedMemorySize, G1_TOTAL);
    cudaFuncSetAttribute(attn_kernel, cudaFuncAttributeMaxDynamicSharedMemorySize, ATT_SMEM);

    // rope inv-freq table
    invf_init_kernel<<<1, 128>>>(invf);

    // conversions
    {
        int n;
        n = M * NHID;        cvt_split_h<<<n/1024, 256>>>(hs, ah, al, n/4);
        n = NH * ND * NHID;  cvt_h<<<n/1024, 256>>>(Wq, wqkv, n/4);
        n = NKV * ND * NHID; cvt_h<<<n/1024, 256>>>(Wk, wqkv + (size_t)2048*NHID, n/4);
        n = NKV * ND * NHID; cvt_h<<<n/1024, 256>>>(Wv, wqkv + (size_t)2560*NHID, n/4);
        n = NHID * NHID;     cvt_h<<<n/1024, 256>>>(Wo, wo, n/4);
    }

    // ONE fused QKV launch (768 CTAs): Q single, K (cols 2048..2559) 2-term, V single
    gemm_mma2<<<dim3(NQKV/128, M/128), 512, GS_TOTAL>>>(ah, al, wqkv, qkvp,
                                                        M, NQKV, NHID, 2048, 2560);

    // rope + per-head layernorm (+ query scaling folded)
    rope_ln_kernel<<<dim3(NB * NS, NH + 2 * NKV), 256>>>(qkvp, invf, Qn, Kn, Vn);

    // 64-row block sums of normalized V
    vblocksum_kernel<<<dim3(NB * NKV, NS / 64), 256>>>(Vn, bs);

    // attention (round-8 best; writes fp16 att directly)
    attn_kernel<<<dim3(NS / AT_BM, NH, NB), 256, ATT_SMEM>>>(Qn, Kn, Vn, bs, oh);

    // output projection: single-term fp16
    gemm_mma1<<<dim3(NHID/128, M/128), 512, G1_TOTAL>>>(oh, wo, out, M, NHID, NHID);
}

// round 15
// speedup vs baseline: 1.0368x; 1.0368x over previous
#include <cuda_runtime.h>
#include <cuda_fp16.h>
#include <math.h>

#define NB   2
#define NS   2048
#define NHID 2048
#define NH   8
#define NKV  2
#define ND   256
#define NSW  512
#define NQKV 3072   // 2048 q + 512 k + 512 v

typedef unsigned long long u64;
typedef unsigned int u32;

__device__ __forceinline__ float2 ffma2(float2 c, float2 a, float2 b) {
    u64 uc = *reinterpret_cast<u64*>(&c);
    u64 ua = *reinterpret_cast<u64*>(&a);
    u64 ub = *reinterpret_cast<u64*>(&b);
    asm("fma.rn.f32x2 %0, %1, %2, %0;" : "+l"(uc) : "l"(ua), "l"(ub));
    float2 r;
    *reinterpret_cast<u64*>(&r) = uc;
    return r;
}

__device__ __forceinline__ u32 smem_u32(const void* p) {
    u32 a;
    asm("{ .reg .u64 t; cvta.to.shared.u64 t, %1; cvt.u32.u64 %0, t; }" : "=r"(a) : "l"(p));
    return a;
}

#define SWZ(o) ((o) ^ (((o) >> 3) & 0x70))

#define CP_ASYNC16(saddr, gptr) \
    asm volatile("cp.async.ca.shared.global [%0], [%1], 16;" :: "r"(saddr), "l"(gptr) : "memory")
#define CP_COMMIT() asm volatile("cp.async.commit_group;" ::: "memory")
#define CP_WAIT1()  asm volatile("cp.async.wait_group 1;" ::: "memory")
#define CP_WAIT0()  asm volatile("cp.async.wait_group 0;" ::: "memory")

#define LDMX4(r0, r1, r2, r3, addr) \
    asm volatile("ldmatrix.sync.aligned.m8n8.x4.shared.b16 {%0,%1,%2,%3}, [%4];" \
        : "=r"(r0), "=r"(r1), "=r"(r2), "=r"(r3) : "r"(addr))

#define MMAF16(d0, d1, d2, d3, a0, a1, a2, a3, b0, b1) \
    asm volatile("mma.sync.aligned.m16n8k16.row.col.f32.f16.f16.f32 " \
        "{%0,%1,%2,%3}, {%4,%5,%6,%7}, {%8,%9}, {%0,%1,%2,%3};" \
        : "+f"(d0), "+f"(d1), "+f"(d2), "+f"(d3) \
        : "r"(a0), "r"(a1), "r"(a2), "r"(a3), "r"(b0), "r"(b1))

// ---------------- scratch ----------------
__device__ float g_qkvp[(size_t)NB*NS*NQKV];
__device__ float g_Q  [(size_t)NB*NH*NS*ND];
__device__ float g_K  [(size_t)NB*NKV*NS*ND];
__device__ float g_V  [(size_t)NB*NKV*NS*ND];
__device__ float g_bs [(size_t)NB*NKV*(NS/64)*ND];
__device__ float g_invf[128];

__device__ __half g_ah[(size_t)NB*NS*NHID], g_al[(size_t)NB*NS*NHID];
__device__ __half g_wqkv[(size_t)NQKV*NHID];
__device__ __half g_wo[(size_t)NHID*NHID];
__device__ __half g_oh[(size_t)NB*NS*NHID];

// ---------------- rope inv-freq table (fp64 once) ----------------
__global__ void invf_init_kernel(float* tab) {
    int j = threadIdx.x;
    tab[j] = (float)exp2(-(double)j * 0.15571537944784511);  // log2(1e6)/128
}

// ---------------- fp32 -> fp16 hi/lo split ----------------
__global__ __launch_bounds__(256) void cvt_split_h(
    const float* __restrict__ x, __half* __restrict__ hi,
    __half* __restrict__ lo, int n4)
{
    int i = blockIdx.x * 256 + threadIdx.x;
    if (i >= n4) return;
    float4 v = *(const float4*)(x + (size_t)i * 4);
    __half h0 = __float2half(v.x), h1 = __float2half(v.y);
    __half h2 = __float2half(v.z), h3 = __float2half(v.w);
    __half l0 = __float2half(v.x - __half2float(h0));
    __half l1 = __float2half(v.y - __half2float(h1));
    __half l2 = __float2half(v.z - __half2float(h2));
    __half l3 = __float2half(v.w - __half2float(h3));
    ushort4 H, L;
    H.x = __half_as_ushort(h0); H.y = __half_as_ushort(h1);
    H.z = __half_as_ushort(h2); H.w = __half_as_ushort(h3);
    L.x = __half_as_ushort(l0); L.y = __half_as_ushort(l1);
    L.z = __half_as_ushort(l2); L.w = __half_as_ushort(l3);
    *(ushort4*)(hi + (size_t)i * 4) = H;
    *(ushort4*)(lo + (size_t)i * 4) = L;
}

// ---------------- fused weight conversion (all 4 weight tensors) ----------
// segments (in 1024-elem blocks): Wq 4096, Wk 1024, Wv 1024, Wo 4096
__global__ __launch_bounds__(256) void cvt_weights(
    const float* __restrict__ Wq, const float* __restrict__ Wk,
    const float* __restrict__ Wv, const float* __restrict__ Wo,
    __half* __restrict__ wqkv, __half* __restrict__ wo)
{
    int blk = blockIdx.x;
    const float* src; __half* dst; int rel;
    if (blk < 4096)      { src = Wq; dst = wqkv;                        rel = blk; }
    else if (blk < 5120) { src = Wk; dst = wqkv + (size_t)2048 * NHID;  rel = blk - 4096; }
    else if (blk < 6144) { src = Wv; dst = wqkv + (size_t)2560 * NHID;  rel = blk - 5120; }
    else                 { src = Wo; dst = wo;                          rel = blk - 6144; }
    int i = rel * 256 + threadIdx.x;
    float4 v = *(const float4*)(src + (size_t)i * 4);
    ushort4 H;
    H.x = __half_as_ushort(__float2half(v.x));
    H.y = __half_as_ushort(__float2half(v.y));
    H.z = __half_as_ushort(__float2half(v.z));
    H.w = __half_as_ushort(__float2half(v.w));
    *(ushort4*)(dst + (size_t)i * 4) = H;
}

// ================= 2-term split GEMM (Ah*B + Al*B, f32 accum) =================
#define GS_STAGE 49152
#define GS_AH 0
#define GS_AL 16384
#define GS_B  32768
#define GS_TOTAL (2 * GS_STAGE)

__global__ __launch_bounds__(512, 2) void gemm_mma2(
    const __half* __restrict__ Ah, const __half* __restrict__ Al,
    const __half* __restrict__ B,
    float* __restrict__ C, int M, int ldc, int K)
{
    extern __shared__ char sm[];
    u32 sb = smem_u32(sm);
    int tid = threadIdx.x;
    int lane = tid & 31, wid = tid >> 5;
    int warpM = wid & 3, warpN = wid >> 2;
    int bm = blockIdx.y * 128, bn = blockIdx.x * 128;

    const int nIt = K >> 6;

    float d[2][4][4];
#pragma unroll
    for (int i = 0; i < 2; i++)
#pragma unroll
        for (int j = 0; j < 4; j++)
#pragma unroll
            for (int c = 0; c < 4; c++) d[i][j][c] = 0.f;

    int lr = tid >> 3, lcb = tid & 7;
    u32 ldo = SWZ((u32)(lr * 128 + lcb * 16));
    size_t gA = (size_t)(bm + lr) * K + lcb * 8;
    size_t gB = (size_t)(bn + lr) * K + lcb * 8;
    size_t rowK64 = (size_t)64 * K;

#pragma unroll
    for (int pit = 0; pit < 2; pit++) {
        u32 stg = sb + pit * GS_STAGE;
        int k0 = pit << 6;
        CP_ASYNC16(stg + GS_AH + ldo,        Ah + gA + k0);
        CP_ASYNC16(stg + GS_AH + ldo + 8192, Ah + gA + rowK64 + k0);
        CP_ASYNC16(stg + GS_AL + ldo,        Al + gA + k0);
        CP_ASYNC16(stg + GS_AL + ldo + 8192, Al + gA + rowK64 + k0);
        CP_ASYNC16(stg + GS_B  + ldo,        B  + gB + k0);
        CP_ASYNC16(stg + GS_B  + ldo + 8192, B  + gB + rowK64 + k0);
        CP_COMMIT();
    }

    u32 arowb[2], axm[2];
#pragma unroll
    for (int i = 0; i < 2; i++) {
        int row = warpM * 32 + i * 16 + (lane & 15);
        arowb[i] = (u32)(row * 128);
        axm[i] = (u32)((row & 7) << 4);
    }
    u32 browb[2], bxm[2];
#pragma unroll
    for (int p = 0; p < 2; p++) {
        int row = warpN * 32 + p * 16 + (lane & 7) + ((lane >> 4) << 3);
        browb[p] = (u32)(row * 128);
        bxm[p] = (u32)((row & 7) << 4);
    }
    u32 colA_base = (u32)((lane >> 4) << 4);
    u32 colB_base = (u32)(((lane >> 3) & 1) << 4);

    for (int it = 0; it < nIt; it++) {
        CP_WAIT1();
        __syncthreads();
        u32 stgA = sb + (it & 1) * GS_STAGE;
#pragma unroll
        for (int kk = 0; kk < 4; kk++) {
            u32 colA = (u32)(kk * 32) + colA_base;
            u32 colB = (u32)(kk * 32) + colB_base;
            u32 ah[2][4], al[2][4], bb[2][4];
#pragma unroll
            for (int i = 0; i < 2; i++) {
                u32 off = arowb[i] + (colA ^ axm[i]);
                LDMX4(ah[i][0], ah[i][1], ah[i][2], ah[i][3], stgA + GS_AH + off);
                LDMX4(al[i][0], al[i][1], al[i][2], al[i][3], stgA + GS_AL + off);
            }
#pragma unroll
            for (int p = 0; p < 2; p++)
                LDMX4(bb[p][0], bb[p][1], bb[p][2], bb[p][3],
                      stgA + GS_B + browb[p] + (colB ^ bxm[p]));
#pragma unroll
            for (int i = 0; i < 2; i++)
#pragma unroll
                for (int j = 0; j < 4; j++) {
                    int p = j >> 1, h2 = (j & 1) << 1;
                    MMAF16(d[i][j][0], d[i][j][1], d[i][j][2], d[i][j][3],
                           ah[i][0], ah[i][1], ah[i][2], ah[i][3],
                           bb[p][h2], bb[p][h2 + 1]);
                }
#pragma unroll
            for (int i = 0; i < 2; i++)
#pragma unroll
                for (int j = 0; j < 4; j++) {
                    int p = j >> 1, h2 = (j & 1) << 1;
                    MMAF16(d[i][j][0], d[i][j][1], d[i][j][2], d[i][j][3],
                           al[i][0], al[i][1], al[i][2], al[i][3],
                           bb[p][h2], bb[p][h2 + 1]);
                }
        }
        __syncthreads();
        if (it + 2 < nIt) {
            u32 stg = sb + (it & 1) * GS_STAGE;
            int k0 = (it + 2) << 6;
            CP_ASYNC16(stg + GS_AH + ldo,        Ah + gA + k0);
            CP_ASYNC16(stg + GS_AH + ldo + 8192, Ah + gA + rowK64 + k0);
            CP_ASYNC16(stg + GS_AL + ldo,        Al + gA + k0);
            CP_ASYNC16(stg + GS_AL + ldo + 8192, Al + gA + rowK64 + k0);
            CP_ASYNC16(stg + GS_B  + ldo,        B  + gB + k0);
            CP_ASYNC16(stg + GS_B  + ldo + 8192, B  + gB + rowK64 + k0);
        }
        CP_COMMIT();
    }
    CP_WAIT0();

#pragma unroll
    for (int i = 0; i < 2; i++) {
#pragma unroll
        for (int j = 0; j < 4; j++) {
            int r0 = bm + warpM * 32 + i * 16 + (lane >> 2);
            int cc = bn + warpN * 32 + j * 8 + (lane & 3) * 2;
            float2 v0 = make_float2(d[i][j][0], d[i][j][1]);
            float2 v1 = make_float2(d[i][j][2], d[i][j][3]);
            *(float2*)(C + (size_t)r0 * ldc + cc) = v0;
            *(float2*)(C + (size_t)(r0 + 8) * ldc + cc) = v1;
        }
    }
}

// ================= single-term GEMM (A*B, f32 accum) =================
#define G1_STAGE 32768
#define G1_A 0
#define G1_B 16384
#define G1_TOTAL (2 * G1_STAGE)

__global__ __launch_bounds__(512, 2) void gemm_mma1(
    const __half* __restrict__ A, const __half* __restrict__ B,
    float* __restrict__ C, int M, int ldc, int K)
{
    extern __shared__ char sm[];
    u32 sb = smem_u32(sm);
    int tid = threadIdx.x;
    int lane = tid & 31, wid = tid >> 5;
    int warpM = wid & 3, warpN = wid >> 2;
    int bm = blockIdx.y * 128, bn = blockIdx.x * 128;

    const int nIt = K >> 6;

    float d[2][4][4];
#pragma unroll
    for (int i = 0; i < 2; i++)
#pragma unroll
        for (int j = 0; j < 4; j++)
#pragma unroll
            for (int c = 0; c < 4; c++) d[i][j][c] = 0.f;

    int lr = tid >> 3, lcb = tid & 7;
    u32 ldo = SWZ((u32)(lr * 128 + lcb * 16));
    size_t gA = (size_t)(bm + lr) * K + lcb * 8;
    size_t gB = (size_t)(bn + lr) * K + lcb * 8;
    size_t rowK64 = (size_t)64 * K;

#pragma unroll
    for (int pit = 0; pit < 2; pit++) {
        u32 stg = sb + pit * G1_STAGE;
        int k0 = pit << 6;
        CP_ASYNC16(stg + G1_A + ldo,        A + gA + k0);
        CP_ASYNC16(stg + G1_A + ldo + 8192, A + gA + rowK64 + k0);
        CP_ASYNC16(stg + G1_B + ldo,        B + gB + k0);
        CP_ASYNC16(stg + G1_B + ldo + 8192, B + gB + rowK64 + k0);
        CP_COMMIT();
    }

    u32 arowb[2], axm[2];
#pragma unroll
    for (int i = 0; i < 2; i++) {
        int row = warpM * 32 + i * 16 + (lane & 15);
        arowb[i] = (u32)(row * 128);
        axm[i] = (u32)((row & 7) << 4);
    }
    u32 browb[2], bxm[2];
#pragma unroll
    for (int p = 0; p < 2; p++) {
        int row = warpN * 32 + p * 16 + (lane & 7) + ((lane >> 4) << 3);
        browb[p] = (u32)(row * 128);
        bxm[p] = (u32)((row & 7) << 4);
    }
    u32 colA_base = (u32)((lane >> 4) << 4);
    u32 colB_base = (u32)(((lane >> 3) & 1) << 4);

    for (int it = 0; it < nIt; it++) {
        CP_WAIT1();
        __syncthreads();
        u32 stgA = sb + (it & 1) * G1_STAGE;
#pragma unroll
        for (int kk = 0; kk < 4; kk++) {
            u32 colA = (u32)(kk * 32) + colA_base;
            u32 colB = (u32)(kk * 32) + colB_base;
            u32 aa[2][4], bb[2][4];
#pragma unroll
            for (int i = 0; i < 2; i++) {
                u32 off = arowb[i] + (colA ^ axm[i]);
                LDMX4(aa[i][0], aa[i][1], aa[i][2], aa[i][3], stgA + G1_A + off);
            }
#pragma unroll
            for (int p = 0; p < 2; p++)
                LDMX4(bb[p][0], bb[p][1], bb[p][2], bb[p][3],
                      stgA + G1_B + browb[p] + (colB ^ bxm[p]));
#pragma unroll
            for (int i = 0; i < 2; i++)
#pragma unroll
                for (int j = 0; j < 4; j++) {
                    int p = j >> 1, h2 = (j & 1) << 1;
                    MMAF16(d[i][j][0], d[i][j][1], d[i][j][2], d[i][j][3],
                           aa[i][0], aa[i][1], aa[i][2], aa[i][3],
                           bb[p][h2], bb[p][h2 + 1]);
                }
        }
        __syncthreads();
        if (it + 2 < nIt) {
            u32 stg = sb + (it & 1) * G1_STAGE;
            int k0 = (it + 2) << 6;
            CP_ASYNC16(stg + G1_A + ldo,        A + gA + k0);
            CP_ASYNC16(stg + G1_A + ldo + 8192, A + gA + rowK64 + k0);
            CP_ASYNC16(stg + G1_B + ldo,        B + gB + k0);
            CP_ASYNC16(stg + G1_B + ldo + 8192, B + gB + rowK64 + k0);
        }
        CP_COMMIT();
    }
    CP_WAIT0();

#pragma unroll
    for (int i = 0; i < 2; i++) {
#pragma unroll
        for (int j = 0; j < 4; j++) {
            int r0 = bm + warpM * 32 + i * 16 + (lane >> 2);
            int cc = bn + warpN * 32 + j * 8 + (lane & 3) * 2;
            float2 v0 = make_float2(d[i][j][0], d[i][j][1]);
            float2 v1 = make_float2(d[i][j][2], d[i][j][3]);
            *(float2*)(C + (size_t)r0 * ldc + cc) = v0;
            *(float2*)(C + (size_t)(r0 + 8) * ldc + cc) = v1;
        }
    }
}

// ---------------- fused RoPE + unit-LayerNorm (+ q scale) ----------------
__global__ __launch_bounds__(256) void rope_ln_kernel(
    const float* __restrict__ qkvp, const float* __restrict__ invf_tab,
    float* __restrict__ Qo, float* __restrict__ Ko, float* __restrict__ Vo)
{
    __shared__ float sh[ND];
    __shared__ float redA[8], redB[8];
    __shared__ float s_mu, s_inv;
    int bs = blockIdx.x;
    int s  = bs & (NS - 1);
    int b  = bs >> 11;
    int u  = blockIdx.y;
    int d  = threadIdx.x;

    const float* src; float* dst; bool doRope; float scale;
    if (u < NH) {
        src = qkvp + (size_t)bs * NQKV + u * ND;
        dst = Qo + (((size_t)(b * NH + u) * NS) + s) * ND;
        doRope = true; scale = 16.0f;
    } else if (u < NH + NKV) {
        int h = u - NH;
        src = qkvp + (size_t)bs * NQKV + 2048 + h * ND;
        dst = Ko + (((size_t)(b * NKV + h) * NS) + s) * ND;
        doRope = true; scale = 1.0f;
    } else {
        int h = u - NH - NKV;
        src = qkvp + (size_t)bs * NQKV + 2560 + h * ND;
        dst = Vo + (((size_t)(b * NKV + h) * NS) + s) * ND;
        doRope = false; scale = 1.0f;
    }

    float x = src[d];
    float r = x;
    if (doRope) {
        sh[d] = x;
        __syncthreads();
        int j = d & 127;
        float invf = invf_tab[j];
        float ang = (float)s * invf;
        float c = cosf(ang), sn = sinf(ang);
        float partner = (d < 128) ? -sh[d + 128] : sh[d - 128];
        r = x * c + partner * sn;
    }
    float s1 = r, s2 = r * r;
#pragma unroll
    for (int off = 16; off; off >>= 1) {
        s1 += __shfl_xor_sync(~0u, s1, off);
        s2 += __shfl_xor_sync(~0u, s2, off);
    }
    int w = d >> 5;
    if ((d & 31) == 0) { redA[w] = s1; redB[w] = s2; }
    __syncthreads();
    if (d == 0) {
        float A = 0.f, Bv = 0.f;
#pragma unroll
        for (int i = 0; i < 8; i++) { A += redA[i]; Bv += redB[i]; }
        float mu  = A * (1.0f / 256.0f);
        float var = Bv * (1.0f / 256.0f) - mu * mu;
        s_mu = mu; s_inv = rsqrtf(var + 1e-6f);
    }
    __syncthreads();
    dst[d] = (r - s_mu) * s_inv * scale;
}

// ---------------- 64-row block sums of V (mask-correction) ----------------
__global__ __launch_bounds__(256) void vblocksum_kernel(
    const float* __restrict__ V, float* __restrict__ BSo)
{
    int bh = blockIdx.x, blk = blockIdx.y, d = threadIdx.x;
    const float* v = V + ((size_t)bh * NS + blk * 64) * ND + d;
    float s = 0.f;
#pragma unroll 8
    for (int i = 0; i < 64; i++) s += v[(size_t)i * ND];
    BSo[((size_t)bh * (NS / 64) + blk) * ND + d] = s;
}

// ---------------- sliding-window softcapped flash attention ----------------
#define AT_BM 64
#define AT_BN 64
#define QS_STR 260
#define KT_STR 68
#define VS_STR 260
#define PS_STR 68
#define ATT_SMEM ((16640 + 17408 + 16640 + 4352 + 256) * 4)

__global__ __launch_bounds__(256, 1) void attn_kernel(
    const float* __restrict__ Q, const float* __restrict__ K,
    const float* __restrict__ V, const float* __restrict__ BS,
    __half* __restrict__ OH)
{
    extern __shared__ __align__(16) float smf[];
    float* Qs    = smf;
    float* Kt    = smf + 16640;
    float* Vs    = smf + 34048;
    float* Ps    = smf + 50688;
    float* corrv = smf + 55040;

    int tid = threadIdx.x;
    int tx = tid & 15, ty = tid >> 4;
    int qt = blockIdx.x, h = blockIdx.y, b = blockIdx.z;
    int qs = qt * AT_BM;
    int kvh = h >> 2;

    const float* Qb = Q + (((size_t)(b * NH  + h  ) * NS) + qs) * ND;
    const float* Kb = K + ((size_t)(b * NKV + kvh) * NS) * ND;
    const float* Vb = V + ((size_t)(b * NKV + kvh) * NS) * ND;
    const float* Bb = BS + (size_t)(b * NKV + kvh) * (NS / 64) * ND;

    int t0 = qs - (NSW - 1);
    int kstart = (t0 <= 0) ? 0 : (t0 & ~63);
    int kend = qs + AT_BM;
    float Ncf = (float)(NS - (kend - kstart));
    int bs0 = kstart >> 6, bs1 = kend >> 6;

    {
        float c = 0.f;
#pragma unroll
        for (int blk = 0; blk < NS / 64; blk++) {
            float x = Bb[(size_t)blk * ND + tid];
            if (blk < bs0 || blk >= bs1) c += x;
        }
        corrv[tid] = c;
    }
#pragma unroll
    for (int it = 0; it < 16; it++) {
        int idx = tid + it * 256;
        int row = idx >> 6, c4 = idx & 63;
        float4 qv = *(const float4*)(Qb + (size_t)row * ND + (c4 << 2));
        float* q = Qs + row * QS_STR + (c4 << 2);
        q[0] = qv.x; q[1] = qv.y; q[2] = qv.z; q[3] = qv.w;
    }

    float2 acc[4][8];
#pragma unroll
    for (int i = 0; i < 4; i++)
#pragma unroll
        for (int c = 0; c < 8; c++) acc[i][c] = make_float2(0.f, 0.f);
    float Mrow[4], Lrow[4];
#pragma unroll
    for (int i = 0; i < 4; i++) { Mrow[i] = -3.0e38f; Lrow[i] = 0.f; }

    for (int k0 = kstart; k0 < kend; k0 += AT_BN) {
        __syncthreads();
#pragma unroll
        for (int it = 0; it < 16; it++) {
            int idx = tid + it * 256;
            int row = idx >> 6, c4 = idx & 63;
            float4 kv = *(const float4*)(Kb + (size_t)(k0 + row) * ND + (c4 << 2));
            Kt[(c4 * 4 + 0) * KT_STR + row] = kv.x;
            Kt[(c4 * 4 + 1) * KT_STR + row] = kv.y;
            Kt[(c4 * 4 + 2) * KT_STR + row] = kv.z;
            Kt[(c4 * 4 + 3) * KT_STR + row] = kv.w;
            float4 vv = *(const float4*)(Vb + (size_t)(k0 + row) * ND + (c4 << 2));
            *(float4*)(Vs + row * VS_STR + (c4 << 2)) = vv;
        }
        __syncthreads();

        float2 s2[4][2];
#pragma unroll
        for (int i = 0; i < 4; i++) { s2[i][0] = make_float2(0.f,0.f); s2[i][1] = make_float2(0.f,0.f); }
        const float* qrow = Qs + (ty << 2) * QS_STR;
#pragma unroll 8
        for (int d = 0; d < ND; d++) {
            float4 kq  = *(const float4*)(Kt + d * KT_STR + (tx << 2));
            float2 b01 = make_float2(kq.x, kq.y);
            float2 b23 = make_float2(kq.z, kq.w);
#pragma unroll
            for (int ii = 0; ii < 4; ii++) {
                float a = qrow[ii * QS_STR + d];
                float2 ap = make_float2(a, a);
                s2[ii][0] = ffma2(s2[ii][0], ap, b01);
                s2[ii][1] = ffma2(s2[ii][1], ap, b23);
            }
        }

#pragma unroll
        for (int ii = 0; ii < 4; ii++) {
            int gi = qs + (ty << 2) + ii;
            float sc[4] = { s2[ii][0].x, s2[ii][0].y, s2[ii][1].x, s2[ii][1].y };
            float rmax = -1e30f;
#pragma unroll
            for (int jj = 0; jj < 4; jj++) {
                int gj = k0 + (tx << 2) + jj;
                float v;
                if (gj <= gi && gj > gi - NSW)
                    v = 30.0f * tanhf(sc[jj] * (1.0f / 30.0f));
                else
                    v = -30.0f;
                sc[jj] = v;
                rmax = fmaxf(rmax, v);
            }
#pragma unroll
            for (int off = 8; off; off >>= 1) rmax = fmaxf(rmax, __shfl_xor_sync(~0u, rmax, off));
            float Mnew = fmaxf(Mrow[ii], rmax);
            float f = expf(Mrow[ii] - Mnew);
            Mrow[ii] = Mnew;
            float rs = 0.f;
#pragma unroll
            for (int jj = 0; jj < 4; jj++) {
                float p = expf(sc[jj] - Mnew);
                Ps[((ty << 2) + ii) * PS_STR + (tx << 2) + jj] = p;
                rs += p;
            }
#pragma unroll
            for (int off = 8; off; off >>= 1) rs += __shfl_xor_sync(~0u, rs, off);
            Lrow[ii] = Lrow[ii] * f + rs;
#pragma unroll
            for (int cc = 0; cc < 8; cc++) { acc[ii][cc].x *= f; acc[ii][cc].y *= f; }
        }
        __syncthreads();

#pragma unroll 4
        for (int kk = 0; kk < AT_BN; kk++) {
            const float* vrow = Vs + kk * VS_STR + (tx << 4);
            float4 v0 = *(const float4*)(vrow);
            float4 v1 = *(const float4*)(vrow + 4);
            float4 v2 = *(const float4*)(vrow + 8);
            float4 v3 = *(const float4*)(vrow + 12);
            float2 vv[8] = {
                make_float2(v0.x,v0.y), make_float2(v0.z,v0.w),
                make_float2(v1.x,v1.y), make_float2(v1.z,v1.w),
                make_float2(v2.x,v2.y), make_float2(v2.z,v2.w),
                make_float2(v3.x,v3.y), make_float2(v3.z,v3.w)
            };
#pragma unroll
            for (int ii = 0; ii < 4; ii++) {
                float p = Ps[((ty << 2) + ii) * PS_STR + kk];
                float2 pp = make_float2(p, p);
#pragma unroll
                for (int cc = 0; cc < 8; cc++) acc[ii][cc] = ffma2(acc[ii][cc], pp, vv[cc]);
            }
        }
    }

    // epilogue: exact masked correction, normalize, write fp16
#pragma unroll
    for (int ii = 0; ii < 4; ii++) {
        float ce = expf(-30.0f - Mrow[ii]);
        float invL = 1.0f / (Lrow[ii] + ce * Ncf);
        int row = qs + (ty << 2) + ii;
        size_t obase = ((size_t)(b * NS + row) * NHID) + h * ND + (tx << 4);
#pragma unroll
        for (int g = 0; g < 4; g++) {
            float2 a0 = acc[ii][g * 2], a1 = acc[ii][g * 2 + 1];
            int c0 = (tx << 4) + g * 4;
            float o0 = (a0.x + ce * corrv[c0 + 0]) * invL;
            float o1 = (a0.y + ce * corrv[c0 + 1]) * invL;
            float o2 = (a1.x + ce * corrv[c0 + 2]) * invL;
            float o3 = (a1.y + ce * corrv[c0 + 3]) * invL;
            ushort4 H;
            H.x = __half_as_ushort(__float2half(o0));
            H.y = __half_as_ushort(__float2half(o1));
            H.z = __half_as_ushort(__float2half(o2));
            H.w = __half_as_ushort(__float2half(o3));
            *(ushort4*)(OH + obase + g * 4) = H;
        }
    }
}

// ---------------- launch ----------------
extern "C" void kernel_launch(void* const* d_in, const int* in_sizes, int n_in,
                              void* d_out, int out_size)
{
    const float* hs = (const float*)d_in[0];
    const float* Wq = (const float*)d_in[1];
    const float* Wk = (const float*)d_in[2];
    const float* Wv = (const float*)d_in[3];
    const float* Wo = (const float*)d_in[4];
    float* out = (float*)d_out;

    float *qkvp, *Qn, *Kn, *Vn, *bs, *invf;
    cudaGetSymbolAddress((void**)&qkvp, g_qkvp);
    cudaGetSymbolAddress((void**)&Qn,  g_Q);
    cudaGetSymbolAddress((void**)&Kn,  g_K);
    cudaGetSymbolAddress((void**)&Vn,  g_V);
    cudaGetSymbolAddress((void**)&bs,  g_bs);
    cudaGetSymbolAddress((void**)&invf, g_invf);

    __half *ah,*al,*wqkv,*wo,*oh;
    cudaGetSymbolAddress((void**)&ah, g_ah); cudaGetSymbolAddress((void**)&al, g_al);
    cudaGetSymbolAddress((void**)&wqkv, g_wqkv);
    cudaGetSymbolAddress((void**)&wo, g_wo);
    cudaGetSymbolAddress((void**)&oh, g_oh);

    const int M = NB * NS;   // 4096

    cudaFuncSetAttribute(gemm_mma2, cudaFuncAttributeMaxDynamicSharedMemorySize, GS_TOTAL);
    cudaFuncSetAttribute(gemm_mma1, cudaFuncAttributeMaxDynamicSharedMemorySize, G1_TOTAL);
    cudaFuncSetAttribute(attn_kernel, cudaFuncAttributeMaxDynamicSharedMemorySize, ATT_SMEM);

    // rope inv-freq table
    invf_init_kernel<<<1, 128>>>(invf);

    // conversions: hs hi/lo split + all weights in one launch
    cvt_split_h<<<(M * NHID) / 1024, 256>>>(hs, ah, al, (M * NHID) / 4);
    cvt_weights<<<10240, 256>>>(Wq, Wk, Wv, Wo, wqkv, wo);

    // Q projection: single-term fp16 (round-12 config)
    gemm_mma1<<<dim3(2048/128, M/128), 512, G1_TOTAL>>>(ah, wqkv, qkvp, M, NQKV, NHID);
    // K/V projections: unconditional 2-term split (round-12 config)
    gemm_mma2<<<dim3(1024/128, M/128), 512, GS_TOTAL>>>(ah, al, wqkv + (size_t)2048*NHID,
                                                        qkvp + 2048, M, NQKV, NHID);

    // rope + per-head layernorm (+ query scaling folded)
    rope_ln_kernel<<<dim3(NB * NS, NH + 2 * NKV), 256>>>(qkvp, invf, Qn, Kn, Vn);

    // 64-row block sums of normalized V
    vblocksum_kernel<<<dim3(NB * NKV, NS / 64), 256>>>(Vn, bs);

    // attention (round-8 best; writes fp16 att directly)
    attn_kernel<<<dim3(NS / AT_BM, NH, NB), 256, ATT_SMEM>>>(Qn, Kn, Vn, bs, oh);

    // output projection: single-term fp16
    gemm_mma1<<<dim3(NHID/128, M/128), 512, G1_TOTAL>>>(oh, wo, out, M, NHID, NHID);
}

// round 16
// speedup vs baseline: 1.4394x; 1.3884x over previous
#include <cuda_runtime.h>
#include <cuda_fp16.h>
#include <math.h>

#define NB   2
#define NS   2048
#define NHID 2048
#define NH   8
#define NKV  2
#define ND   256
#define NSW  512
#define NQKV 3072   // 2048 q + 512 k + 512 v

typedef unsigned long long u64;
typedef unsigned int u32;

__device__ __forceinline__ float2 ffma2(float2 c, float2 a, float2 b) {
    u64 uc = *reinterpret_cast<u64*>(&c);
    u64 ua = *reinterpret_cast<u64*>(&a);
    u64 ub = *reinterpret_cast<u64*>(&b);
    asm("fma.rn.f32x2 %0, %1, %2, %0;" : "+l"(uc) : "l"(ua), "l"(ub));
    float2 r;
    *reinterpret_cast<u64*>(&r) = uc;
    return r;
}

__device__ __forceinline__ u32 smem_u32(const void* p) {
    u32 a;
    asm("{ .reg .u64 t; cvta.to.shared.u64 t, %1; cvt.u32.u64 %0, t; }" : "=r"(a) : "l"(p));
    return a;
}

#define SWZ(o) ((o) ^ (((o) >> 3) & 0x70))

#define CP_ASYNC16(saddr, gptr) \
    asm volatile("cp.async.ca.shared.global [%0], [%1], 16;" :: "r"(saddr), "l"(gptr) : "memory")
#define CP_COMMIT() asm volatile("cp.async.commit_group;" ::: "memory")
#define CP_WAIT1()  asm volatile("cp.async.wait_group 1;" ::: "memory")
#define CP_WAIT0()  asm volatile("cp.async.wait_group 0;" ::: "memory")

#define LDMX4(r0, r1, r2, r3, addr) \
    asm volatile("ldmatrix.sync.aligned.m8n8.x4.shared.b16 {%0,%1,%2,%3}, [%4];" \
        : "=r"(r0), "=r"(r1), "=r"(r2), "=r"(r3) : "r"(addr))

#define MMAF16(d0, d1, d2, d3, a0, a1, a2, a3, b0, b1) \
    asm volatile("mma.sync.aligned.m16n8k16.row.col.f32.f16.f16.f32 " \
        "{%0,%1,%2,%3}, {%4,%5,%6,%7}, {%8,%9}, {%0,%1,%2,%3};" \
        : "+f"(d0), "+f"(d1), "+f"(d2), "+f"(d3) \
        : "r"(a0), "r"(a1), "r"(a2), "r"(a3), "r"(b0), "r"(b1))

// ---------------- scratch ----------------
__device__ float g_qkvp[(size_t)NB*NS*NQKV];
__device__ float g_Q  [(size_t)NB*NH*NS*ND];
__device__ float g_K  [(size_t)NB*NKV*NS*ND];
__device__ float g_V  [(size_t)NB*NKV*NS*ND];
__device__ float g_bs [(size_t)NB*NKV*(NS/64)*ND];
__device__ float g_invf[128];

__device__ __half g_ah[(size_t)NB*NS*NHID], g_al[(size_t)NB*NS*NHID];
__device__ __half g_wqkv[(size_t)NQKV*NHID];
__device__ __half g_wo[(size_t)NHID*NHID];
__device__ __half g_oh[(size_t)NB*NS*NHID];

// ---------------- rope inv-freq table (fp64 once) ----------------
__global__ void invf_init_kernel(float* tab) {
    int j = threadIdx.x;
    tab[j] = (float)exp2(-(double)j * 0.15571537944784511);  // log2(1e6)/128
}

// ---------------- fp32 -> fp16 hi/lo split ----------------
__global__ __launch_bounds__(256) void cvt_split_h(
    const float* __restrict__ x, __half* __restrict__ hi,
    __half* __restrict__ lo, int n4)
{
    int i = blockIdx.x * 256 + threadIdx.x;
    if (i >= n4) return;
    float4 v = *(const float4*)(x + (size_t)i * 4);
    __half h0 = __float2half(v.x), h1 = __float2half(v.y);
    __half h2 = __float2half(v.z), h3 = __float2half(v.w);
    __half l0 = __float2half(v.x - __half2float(h0));
    __half l1 = __float2half(v.y - __half2float(h1));
    __half l2 = __float2half(v.z - __half2float(h2));
    __half l3 = __float2half(v.w - __half2float(h3));
    ushort4 H, L;
    H.x = __half_as_ushort(h0); H.y = __half_as_ushort(h1);
    H.z = __half_as_ushort(h2); H.w = __half_as_ushort(h3);
    L.x = __half_as_ushort(l0); L.y = __half_as_ushort(l1);
    L.z = __half_as_ushort(l2); L.w = __half_as_ushort(l3);
    *(ushort4*)(hi + (size_t)i * 4) = H;
    *(ushort4*)(lo + (size_t)i * 4) = L;
}

// ---------------- fused weight conversion ----------------
__global__ __launch_bounds__(256) void cvt_weights(
    const float* __restrict__ Wq, const float* __restrict__ Wk,
    const float* __restrict__ Wv, const float* __restrict__ Wo,
    __half* __restrict__ wqkv, __half* __restrict__ wo)
{
    int blk = blockIdx.x;
    const float* src; __half* dst; int rel;
    if (blk < 4096)      { src = Wq; dst = wqkv;                        rel = blk; }
    else if (blk < 5120) { src = Wk; dst = wqkv + (size_t)2048 * NHID;  rel = blk - 4096; }
    else if (blk < 6144) { src = Wv; dst = wqkv + (size_t)2560 * NHID;  rel = blk - 5120; }
    else                 { src = Wo; dst = wo;                          rel = blk - 6144; }
    int i = rel * 256 + threadIdx.x;
    float4 v = *(const float4*)(src + (size_t)i * 4);
    ushort4 H;
    H.x = __half_as_ushort(__float2half(v.x));
    H.y = __half_as_ushort(__float2half(v.y));
    H.z = __half_as_ushort(__float2half(v.z));
    H.w = __half_as_ushort(__float2half(v.w));
    *(ushort4*)(dst + (size_t)i * 4) = H;
}

// ================= 2-term split GEMM (Ah*B + Al*B, f32 accum) =================
#define GS_STAGE 49152
#define GS_AH 0
#define GS_AL 16384
#define GS_B  32768
#define GS_TOTAL (2 * GS_STAGE)

__global__ __launch_bounds__(512, 2) void gemm_mma2(
    const __half* __restrict__ Ah, const __half* __restrict__ Al,
    const __half* __restrict__ B,
    float* __restrict__ C, int M, int ldc, int K)
{
    extern __shared__ char sm[];
    u32 sb = smem_u32(sm);
    int tid = threadIdx.x;
    int lane = tid & 31, wid = tid >> 5;
    int warpM = wid & 3, warpN = wid >> 2;
    int bm = blockIdx.y * 128, bn = blockIdx.x * 128;

    const int nIt = K >> 6;

    float d[2][4][4];
#pragma unroll
    for (int i = 0; i < 2; i++)
#pragma unroll
        for (int j = 0; j < 4; j++)
#pragma unroll
            for (int c = 0; c < 4; c++) d[i][j][c] = 0.f;

    int lr = tid >> 3, lcb = tid & 7;
    u32 ldo = SWZ((u32)(lr * 128 + lcb * 16));
    size_t gA = (size_t)(bm + lr) * K + lcb * 8;
    size_t gB = (size_t)(bn + lr) * K + lcb * 8;
    size_t rowK64 = (size_t)64 * K;

#pragma unroll
    for (int pit = 0; pit < 2; pit++) {
        u32 stg = sb + pit * GS_STAGE;
        int k0 = pit << 6;
        CP_ASYNC16(stg + GS_AH + ldo,        Ah + gA + k0);
        CP_ASYNC16(stg + GS_AH + ldo + 8192, Ah + gA + rowK64 + k0);
        CP_ASYNC16(stg + GS_AL + ldo,        Al + gA + k0);
        CP_ASYNC16(stg + GS_AL + ldo + 8192, Al + gA + rowK64 + k0);
        CP_ASYNC16(stg + GS_B  + ldo,        B  + gB + k0);
        CP_ASYNC16(stg + GS_B  + ldo + 8192, B  + gB + rowK64 + k0);
        CP_COMMIT();
    }

    u32 arowb[2], axm[2];
#pragma unroll
    for (int i = 0; i < 2; i++) {
        int row = warpM * 32 + i * 16 + (lane & 15);
        arowb[i] = (u32)(row * 128);
        axm[i] = (u32)((row & 7) << 4);
    }
    u32 browb[2], bxm[2];
#pragma unroll
    for (int p = 0; p < 2; p++) {
        int row = warpN * 32 + p * 16 + (lane & 7) + ((lane >> 4) << 3);
        browb[p] = (u32)(row * 128);
        bxm[p] = (u32)((row & 7) << 4);
    }
    u32 colA_base = (u32)((lane >> 4) << 4);
    u32 colB_base = (u32)(((lane >> 3) & 1) << 4);

    for (int it = 0; it < nIt; it++) {
        CP_WAIT1();
        __syncthreads();
        u32 stgA = sb + (it & 1) * GS_STAGE;
#pragma unroll
        for (int kk = 0; kk < 4; kk++) {
            u32 colA = (u32)(kk * 32) + colA_base;
            u32 colB = (u32)(kk * 32) + colB_base;
            u32 ah[2][4], al[2][4], bb[2][4];
#pragma unroll
            for (int i = 0; i < 2; i++) {
                u32 off = arowb[i] + (colA ^ axm[i]);
                LDMX4(ah[i][0], ah[i][1], ah[i][2], ah[i][3], stgA + GS_AH + off);
                LDMX4(al[i][0], al[i][1], al[i][2], al[i][3], stgA + GS_AL + off);
            }
#pragma unroll
            for (int p = 0; p < 2; p++)
                LDMX4(bb[p][0], bb[p][1], bb[p][2], bb[p][3],
                      stgA + GS_B + browb[p] + (colB ^ bxm[p]));
#pragma unroll
            for (int i = 0; i < 2; i++)
#pragma unroll
                for (int j = 0; j < 4; j++) {
                    int p = j >> 1, h2 = (j & 1) << 1;
                    MMAF16(d[i][j][0], d[i][j][1], d[i][j][2], d[i][j][3],
                           ah[i][0], ah[i][1], ah[i][2], ah[i][3],
                           bb[p][h2], bb[p][h2 + 1]);
                }
#pragma unroll
            for (int i = 0; i < 2; i++)
#pragma unroll
                for (int j = 0; j < 4; j++) {
                    int p = j >> 1, h2 = (j & 1) << 1;
                    MMAF16(d[i][j][0], d[i][j][1], d[i][j][2], d[i][j][3],
                           al[i][0], al[i][1], al[i][2], al[i][3],
                           bb[p][h2], bb[p][h2 + 1]);
                }
        }
        __syncthreads();
        if (it + 2 < nIt) {
            u32 stg = sb + (it & 1) * GS_STAGE;
            int k0 = (it + 2) << 6;
            CP_ASYNC16(stg + GS_AH + ldo,        Ah + gA + k0);
            CP_ASYNC16(stg + GS_AH + ldo + 8192, Ah + gA + rowK64 + k0);
            CP_ASYNC16(stg + GS_AL + ldo,        Al + gA + k0);
            CP_ASYNC16(stg + GS_AL + ldo + 8192, Al + gA + rowK64 + k0);
            CP_ASYNC16(stg + GS_B  + ldo,        B  + gB + k0);
            CP_ASYNC16(stg + GS_B  + ldo + 8192, B  + gB + rowK64 + k0);
        }
        CP_COMMIT();
    }
    CP_WAIT0();

#pragma unroll
    for (int i = 0; i < 2; i++) {
#pragma unroll
        for (int j = 0; j < 4; j++) {
            int r0 = bm + warpM * 32 + i * 16 + (lane >> 2);
            int cc = bn + warpN * 32 + j * 8 + (lane & 3) * 2;
            float2 v0 = make_float2(d[i][j][0], d[i][j][1]);
            float2 v1 = make_float2(d[i][j][2], d[i][j][3]);
            *(float2*)(C + (size_t)r0 * ldc + cc) = v0;
            *(float2*)(C + (size_t)(r0 + 8) * ldc + cc) = v1;
        }
    }
}

// ================= single-term GEMM (A*B, f32 accum) =================
#define G1_STAGE 32768
#define G1_A 0
#define G1_B 16384
#define G1_TOTAL (2 * G1_STAGE)

__global__ __launch_bounds__(512, 2) void gemm_mma1(
    const __half* __restrict__ A, const __half* __restrict__ B,
    float* __restrict__ C, int M, int ldc, int K)
{
    extern __shared__ char sm[];
    u32 sb = smem_u32(sm);
    int tid = threadIdx.x;
    int lane = tid & 31, wid = tid >> 5;
    int warpM = wid & 3, warpN = wid >> 2;
    int bm = blockIdx.y * 128, bn = blockIdx.x * 128;

    const int nIt = K >> 6;

    float d[2][4][4];
#pragma unroll
    for (int i = 0; i < 2; i++)
#pragma unroll
        for (int j = 0; j < 4; j++)
#pragma unroll
            for (int c = 0; c < 4; c++) d[i][j][c] = 0.f;

    int lr = tid >> 3, lcb = tid & 7;
    u32 ldo = SWZ((u32)(lr * 128 + lcb * 16));
    size_t gA = (size_t)(bm + lr) * K + lcb * 8;
    size_t gB = (size_t)(bn + lr) * K + lcb * 8;
    size_t rowK64 = (size_t)64 * K;

#pragma unroll
    for (int pit = 0; pit < 2; pit++) {
        u32 stg = sb + pit * G1_STAGE;
        int k0 = pit << 6;
        CP_ASYNC16(stg + G1_A + ldo,        A + gA + k0);
        CP_ASYNC16(stg + G1_A + ldo + 8192, A + gA + rowK64 + k0);
        CP_ASYNC16(stg + G1_B + ldo,        B + gB + k0);
        CP_ASYNC16(stg + G1_B + ldo + 8192, B + gB + rowK64 + k0);
        CP_COMMIT();
    }

    u32 arowb[2], axm[2];
#pragma unroll
    for (int i = 0; i < 2; i++) {
        int row = warpM * 32 + i * 16 + (lane & 15);
        arowb[i] = (u32)(row * 128);
        axm[i] = (u32)((row & 7) << 4);
    }
    u32 browb[2], bxm[2];
#pragma unroll
    for (int p = 0; p < 2; p++) {
        int row = warpN * 32 + p * 16 + (lane & 7) + ((lane >> 4) << 3);
        browb[p] = (u32)(row * 128);
        bxm[p] = (u32)((row & 7) << 4);
    }
    u32 colA_base = (u32)((lane >> 4) << 4);
    u32 colB_base = (u32)(((lane >> 3) & 1) << 4);

    for (int it = 0; it < nIt; it++) {
        CP_WAIT1();
        __syncthreads();
        u32 stgA = sb + (it & 1) * G1_STAGE;
#pragma unroll
        for (int kk = 0; kk < 4; kk++) {
            u32 colA = (u32)(kk * 32) + colA_base;
            u32 colB = (u32)(kk * 32) + colB_base;
            u32 aa[2][4], bb[2][4];
#pragma unroll
            for (int i = 0; i < 2; i++) {
                u32 off = arowb[i] + (colA ^ axm[i]);
                LDMX4(aa[i][0], aa[i][1], aa[i][2], aa[i][3], stgA + G1_A + off);
            }
#pragma unroll
            for (int p = 0; p < 2; p++)
                LDMX4(bb[p][0], bb[p][1], bb[p][2], bb[p][3],
                      stgA + G1_B + browb[p] + (colB ^ bxm[p]));
#pragma unroll
            for (int i = 0; i < 2; i++)
#pragma unroll
                for (int j = 0; j < 4; j++) {
                    int p = j >> 1, h2 = (j & 1) << 1;
                    MMAF16(d[i][j][0], d[i][j][1], d[i][j][2], d[i][j][3],
                           aa[i][0], aa[i][1], aa[i][2], aa[i][3],
                           bb[p][h2], bb[p][h2 + 1]);
                }
        }
        __syncthreads();
        if (it + 2 < nIt) {
            u32 stg = sb + (it & 1) * G1_STAGE;
            int k0 = (it + 2) << 6;
            CP_ASYNC16(stg + G1_A + ldo,        A + gA + k0);
            CP_ASYNC16(stg + G1_A + ldo + 8192, A + gA + rowK64 + k0);
            CP_ASYNC16(stg + G1_B + ldo,        B + gB + k0);
            CP_ASYNC16(stg + G1_B + ldo + 8192, B + gB + rowK64 + k0);
        }
        CP_COMMIT();
    }
    CP_WAIT0();

#pragma unroll
    for (int i = 0; i < 2; i++) {
#pragma unroll
        for (int j = 0; j < 4; j++) {
            int r0 = bm + warpM * 32 + i * 16 + (lane >> 2);
            int cc = bn + warpN * 32 + j * 8 + (lane & 3) * 2;
            float2 v0 = make_float2(d[i][j][0], d[i][j][1]);
            float2 v1 = make_float2(d[i][j][2], d[i][j][3]);
            *(float2*)(C + (size_t)r0 * ldc + cc) = v0;
            *(float2*)(C + (size_t)(r0 + 8) * ldc + cc) = v1;
        }
    }
}

// ---------------- fused RoPE + unit-LayerNorm (+ q scale) ----------------
__global__ __launch_bounds__(256) void rope_ln_kernel(
    const float* __restrict__ qkvp, const float* __restrict__ invf_tab,
    float* __restrict__ Qo, float* __restrict__ Ko, float* __restrict__ Vo)
{
    __shared__ float sh[ND];
    __shared__ float redA[8], redB[8];
    __shared__ float s_mu, s_inv;
    int bs = blockIdx.x;
    int s  = bs & (NS - 1);
    int b  = bs >> 11;
    int u  = blockIdx.y;
    int d  = threadIdx.x;

    const float* src; float* dst; bool doRope; float scale;
    if (u < NH) {
        src = qkvp + (size_t)bs * NQKV + u * ND;
        dst = Qo + (((size_t)(b * NH + u) * NS) + s) * ND;
        doRope = true; scale = 16.0f;
    } else if (u < NH + NKV) {
        int h = u - NH;
        src = qkvp + (size_t)bs * NQKV + 2048 + h * ND;
        dst = Ko + (((size_t)(b * NKV + h) * NS) + s) * ND;
        doRope = true; scale = 1.0f;
    } else {
        int h = u - NH - NKV;
        src = qkvp + (size_t)bs * NQKV + 2560 + h * ND;
        dst = Vo + (((size_t)(b * NKV + h) * NS) + s) * ND;
        doRope = false; scale = 1.0f;
    }

    float x = src[d];
    float r = x;
    if (doRope) {
        sh[d] = x;
        __syncthreads();
        int j = d & 127;
        float invf = invf_tab[j];
        float ang = (float)s * invf;
        float c = cosf(ang), sn = sinf(ang);
        float partner = (d < 128) ? -sh[d + 128] : sh[d - 128];
        r = x * c + partner * sn;
    }
    float s1 = r, s2 = r * r;
#pragma unroll
    for (int off = 16; off; off >>= 1) {
        s1 += __shfl_xor_sync(~0u, s1, off);
        s2 += __shfl_xor_sync(~0u, s2, off);
    }
    int w = d >> 5;
    if ((d & 31) == 0) { redA[w] = s1; redB[w] = s2; }
    __syncthreads();
    if (d == 0) {
        float A = 0.f, Bv = 0.f;
#pragma unroll
        for (int i = 0; i < 8; i++) { A += redA[i]; Bv += redB[i]; }
        float mu  = A * (1.0f / 256.0f);
        float var = Bv * (1.0f / 256.0f) - mu * mu;
        s_mu = mu; s_inv = rsqrtf(var + 1e-6f);
    }
    __syncthreads();
    dst[d] = (r - s_mu) * s_inv * scale;
}

// ---------------- 64-row block sums of V (mask-correction) ----------------
__global__ __launch_bounds__(256) void vblocksum_kernel(
    const float* __restrict__ V, float* __restrict__ BSo)
{
    int bh = blockIdx.x, blk = blockIdx.y, d = threadIdx.x;
    const float* v = V + ((size_t)bh * NS + blk * 64) * ND + d;
    float s = 0.f;
#pragma unroll 8
    for (int i = 0; i < 64; i++) s += v[(size_t)i * ND];
    BSo[((size_t)bh * (NS / 64) + blk) * ND + d] = s;
}

// ---------------- sliding-window softcapped flash attention ----------------
// PV V-columns interleaved per thread: cols {4*tx + 64*g}, g=0..3
// (bank-conflict-free LDS.128: 2 wavefronts vs 8 with contiguous mapping)
#define AT_BM 64
#define AT_BN 64
#define QS_STR 260
#define KT_STR 68
#define VS_STR 260
#define PS_STR 68
#define ATT_SMEM ((16640 + 17408 + 16640 + 4352 + 256) * 4)

__global__ __launch_bounds__(256, 1) void attn_kernel(
    const float* __restrict__ Q, const float* __restrict__ K,
    const float* __restrict__ V, const float* __restrict__ BS,
    __half* __restrict__ OH)
{
    extern __shared__ __align__(16) float smf[];
    float* Qs    = smf;
    float* Kt    = smf + 16640;
    float* Vs    = smf + 34048;
    float* Ps    = smf + 50688;
    float* corrv = smf + 55040;

    int tid = threadIdx.x;
    int tx = tid & 15, ty = tid >> 4;
    int qt = blockIdx.x, h = blockIdx.y, b = blockIdx.z;
    int qs = qt * AT_BM;
    int kvh = h >> 2;

    const float* Qb = Q + (((size_t)(b * NH  + h  ) * NS) + qs) * ND;
    const float* Kb = K + ((size_t)(b * NKV + kvh) * NS) * ND;
    const float* Vb = V + ((size_t)(b * NKV + kvh) * NS) * ND;
    const float* Bb = BS + (size_t)(b * NKV + kvh) * (NS / 64) * ND;

    int t0 = qs - (NSW - 1);
    int kstart = (t0 <= 0) ? 0 : (t0 & ~63);
    int kend = qs + AT_BM;
    float Ncf = (float)(NS - (kend - kstart));
    int bs0 = kstart >> 6, bs1 = kend >> 6;

    {
        float c = 0.f;
#pragma unroll
        for (int blk = 0; blk < NS / 64; blk++) {
            float x = Bb[(size_t)blk * ND + tid];
            if (blk < bs0 || blk >= bs1) c += x;
        }
        corrv[tid] = c;
    }
#pragma unroll
    for (int it = 0; it < 16; it++) {
        int idx = tid + it * 256;
        int row = idx >> 6, c4 = idx & 63;
        float4 qv = *(const float4*)(Qb + (size_t)row * ND + (c4 << 2));
        float* q = Qs + row * QS_STR + (c4 << 2);
        q[0] = qv.x; q[1] = qv.y; q[2] = qv.z; q[3] = qv.w;
    }

    float2 acc[4][8];
#pragma unroll
    for (int i = 0; i < 4; i++)
#pragma unroll
        for (int c = 0; c < 8; c++) acc[i][c] = make_float2(0.f, 0.f);
    float Mrow[4], Lrow[4];
#pragma unroll
    for (int i = 0; i < 4; i++) { Mrow[i] = -3.0e38f; Lrow[i] = 0.f; }

    for (int k0 = kstart; k0 < kend; k0 += AT_BN) {
        __syncthreads();
#pragma unroll
        for (int it = 0; it < 16; it++) {
            int idx = tid + it * 256;
            int row = idx >> 6, c4 = idx & 63;
            float4 kv = *(const float4*)(Kb + (size_t)(k0 + row) * ND + (c4 << 2));
            Kt[(c4 * 4 + 0) * KT_STR + row] = kv.x;
            Kt[(c4 * 4 + 1) * KT_STR + row] = kv.y;
            Kt[(c4 * 4 + 2) * KT_STR + row] = kv.z;
            Kt[(c4 * 4 + 3) * KT_STR + row] = kv.w;
            float4 vv = *(const float4*)(Vb + (size_t)(k0 + row) * ND + (c4 << 2));
            *(float4*)(Vs + row * VS_STR + (c4 << 2)) = vv;
        }
        __syncthreads();

        float2 s2[4][2];
#pragma unroll
        for (int i = 0; i < 4; i++) { s2[i][0] = make_float2(0.f,0.f); s2[i][1] = make_float2(0.f,0.f); }
        const float* qrow = Qs + (ty << 2) * QS_STR;
#pragma unroll 8
        for (int d = 0; d < ND; d++) {
            float4 kq  = *(const float4*)(Kt + d * KT_STR + (tx << 2));
            float2 b01 = make_float2(kq.x, kq.y);
            float2 b23 = make_float2(kq.z, kq.w);
#pragma unroll
            for (int ii = 0; ii < 4; ii++) {
                float a = qrow[ii * QS_STR + d];
                float2 ap = make_float2(a, a);
                s2[ii][0] = ffma2(s2[ii][0], ap, b01);
                s2[ii][1] = ffma2(s2[ii][1], ap, b23);
            }
        }

#pragma unroll
        for (int ii = 0; ii < 4; ii++) {
            int gi = qs + (ty << 2) + ii;
            float sc[4] = { s2[ii][0].x, s2[ii][0].y, s2[ii][1].x, s2[ii][1].y };
            float rmax = -1e30f;
#pragma unroll
            for (int jj = 0; jj < 4; jj++) {
                int gj = k0 + (tx << 2) + jj;
                float v;
                if (gj <= gi && gj > gi - NSW)
                    v = 30.0f * tanhf(sc[jj] * (1.0f / 30.0f));
                else
                    v = -30.0f;
                sc[jj] = v;
                rmax = fmaxf(rmax, v);
            }
#pragma unroll
            for (int off = 8; off; off >>= 1) rmax = fmaxf(rmax, __shfl_xor_sync(~0u, rmax, off));
            float Mnew = fmaxf(Mrow[ii], rmax);
            float f = expf(Mrow[ii] - Mnew);
            Mrow[ii] = Mnew;
            float rs = 0.f;
#pragma unroll
            for (int jj = 0; jj < 4; jj++) {
                float p = expf(sc[jj] - Mnew);
                Ps[((ty << 2) + ii) * PS_STR + (tx << 2) + jj] = p;
                rs += p;
            }
#pragma unroll
            for (int off = 8; off; off >>= 1) rs += __shfl_xor_sync(~0u, rs, off);
            Lrow[ii] = Lrow[ii] * f + rs;
#pragma unroll
            for (int cc = 0; cc < 8; cc++) { acc[ii][cc].x *= f; acc[ii][cc].y *= f; }
        }
        __syncthreads();

        // PV with interleaved column ownership: cols {4tx + 64g}
#pragma unroll 4
        for (int kk = 0; kk < AT_BN; kk++) {
            const float* vrow = Vs + kk * VS_STR + (tx << 2);
            float4 v0 = *(const float4*)(vrow);
            float4 v1 = *(const float4*)(vrow + 64);
            float4 v2 = *(const float4*)(vrow + 128);
            float4 v3 = *(const float4*)(vrow + 192);
            float2 vv[8] = {
                make_float2(v0.x,v0.y), make_float2(v0.z,v0.w),
                make_float2(v1.x,v1.y), make_float2(v1.z,v1.w),
                make_float2(v2.x,v2.y), make_float2(v2.z,v2.w),
                make_float2(v3.x,v3.y), make_float2(v3.z,v3.w)
            };
#pragma unroll
            for (int ii = 0; ii < 4; ii++) {
                float p = Ps[((ty << 2) + ii) * PS_STR + kk];
                float2 pp = make_float2(p, p);
#pragma unroll
                for (int cc = 0; cc < 8; cc++) acc[ii][cc] = ffma2(acc[ii][cc], pp, vv[cc]);
            }
        }
    }

    // epilogue: exact masked correction, normalize, write fp16 (interleaved cols)
#pragma unroll
    for (int ii = 0; ii < 4; ii++) {
        float ce = expf(-30.0f - Mrow[ii]);
        float invL = 1.0f / (Lrow[ii] + ce * Ncf);
        int row = qs + (ty << 2) + ii;
        size_t obase = ((size_t)(b * NS + row) * NHID) + h * ND;
#pragma unroll
        for (int g = 0; g < 4; g++) {
            float2 a0 = acc[ii][g * 2], a1 = acc[ii][g * 2 + 1];
            int c0 = (tx << 2) + g * 64;
            float o0 = (a0.x + ce * corrv[c0 + 0]) * invL;
            float o1 = (a0.y + ce * corrv[c0 + 1]) * invL;
            float o2 = (a1.x + ce * corrv[c0 + 2]) * invL;
            float o3 = (a1.y + ce * corrv[c0 + 3]) * invL;
            ushort4 H;
            H.x = __half_as_ushort(__float2half(o0));
            H.y = __half_as_ushort(__float2half(o1));
            H.z = __half_as_ushort(__float2half(o2));
            H.w = __half_as_ushort(__float2half(o3));
            *(ushort4*)(OH + obase + c0) = H;
        }
    }
}

// ---------------- launch ----------------
extern "C" void kernel_launch(void* const* d_in, const int* in_sizes, int n_in,
                              void* d_out, int out_size)
{
    const float* hs = (const float*)d_in[0];
    const float* Wq = (const float*)d_in[1];
    const float* Wk = (const float*)d_in[2];
    const float* Wv = (const float*)d_in[3];
    const float* Wo = (const float*)d_in[4];
    float* out = (float*)d_out;

    float *qkvp, *Qn, *Kn, *Vn, *bs, *invf;
    cudaGetSymbolAddress((void**)&qkvp, g_qkvp);
    cudaGetSymbolAddress((void**)&Qn,  g_Q);
    cudaGetSymbolAddress((void**)&Kn,  g_K);
    cudaGetSymbolAddress((void**)&Vn,  g_V);
    cudaGetSymbolAddress((void**)&bs,  g_bs);
    cudaGetSymbolAddress((void**)&invf, g_invf);

    __half *ah,*al,*wqkv,*wo,*oh;
    cudaGetSymbolAddress((void**)&ah, g_ah); cudaGetSymbolAddress((void**)&al, g_al);
    cudaGetSymbolAddress((void**)&wqkv, g_wqkv);
    cudaGetSymbolAddress((void**)&wo, g_wo);
    cudaGetSymbolAddress((void**)&oh, g_oh);

    const int M = NB * NS;   // 4096

    cudaFuncSetAttribute(gemm_mma2, cudaFuncAttributeMaxDynamicSharedMemorySize, GS_TOTAL);
    cudaFuncSetAttribute(gemm_mma1, cudaFuncAttributeMaxDynamicSharedMemorySize, G1_TOTAL);
    cudaFuncSetAttribute(attn_kernel, cudaFuncAttributeMaxDynamicSharedMemorySize, ATT_SMEM);

    // rope inv-freq table
    invf_init_kernel<<<1, 128>>>(invf);

    // conversions: hs hi/lo split + all weights in one launch
    cvt_split_h<<<(M * NHID) / 1024, 256>>>(hs, ah, al, (M * NHID) / 4);
    cvt_weights<<<10240, 256>>>(Wq, Wk, Wv, Wo, wqkv, wo);

    // Q projection: single-term fp16
    gemm_mma1<<<dim3(2048/128, M/128), 512, G1_TOTAL>>>(ah, wqkv, qkvp, M, NQKV, NHID);
    // K/V projections: 2-term split
    gemm_mma2<<<dim3(1024/128, M/128), 512, GS_TOTAL>>>(ah, al, wqkv + (size_t)2048*NHID,
                                                        qkvp + 2048, M, NQKV, NHID);

    // rope + per-head layernorm (+ query scaling folded)
    rope_ln_kernel<<<dim3(NB * NS, NH + 2 * NKV), 256>>>(qkvp, invf, Qn, Kn, Vn);

    // 64-row block sums of normalized V
    vblocksum_kernel<<<dim3(NB * NKV, NS / 64), 256>>>(Vn, bs);

    // attention (conflict-free PV)
    attn_kernel<<<dim3(NS / AT_BM, NH, NB), 256, ATT_SMEM>>>(Qn, Kn, Vn, bs, oh);

    // output projection: single-term fp16
    gemm_mma1<<<dim3(NHID/128, M/128), 512, G1_TOTAL>>>(oh, wo, out, M, NHID, NHID);
}

// round 17
// speedup vs baseline: 1.5603x; 1.0840x over previous
#include <cuda_runtime.h>
#include <cuda_fp16.h>
#include <math.h>

#define NB   2
#define NS   2048
#define NHID 2048
#define NH   8
#define NKV  2
#define ND   256
#define NSW  512
#define NQKV 3072   // 2048 q + 512 k + 512 v

typedef unsigned long long u64;
typedef unsigned int u32;

__device__ __forceinline__ float2 ffma2(float2 c, float2 a, float2 b) {
    u64 uc = *reinterpret_cast<u64*>(&c);
    u64 ua = *reinterpret_cast<u64*>(&a);
    u64 ub = *reinterpret_cast<u64*>(&b);
    asm("fma.rn.f32x2 %0, %1, %2, %0;" : "+l"(uc) : "l"(ua), "l"(ub));
    float2 r;
    *reinterpret_cast<u64*>(&r) = uc;
    return r;
}

__device__ __forceinline__ u32 smem_u32(const void* p) {
    u32 a;
    asm("{ .reg .u64 t; cvta.to.shared.u64 t, %1; cvt.u32.u64 %0, t; }" : "=r"(a) : "l"(p));
    return a;
}

#define SWZ(o) ((o) ^ (((o) >> 3) & 0x70))

#define CP_ASYNC16(saddr, gptr) \
    asm volatile("cp.async.ca.shared.global [%0], [%1], 16;" :: "r"(saddr), "l"(gptr) : "memory")
#define CP_COMMIT() asm volatile("cp.async.commit_group;" ::: "memory")
#define CP_WAIT1()  asm volatile("cp.async.wait_group 1;" ::: "memory")
#define CP_WAIT0()  asm volatile("cp.async.wait_group 0;" ::: "memory")

#define LDMX4(r0, r1, r2, r3, addr) \
    asm volatile("ldmatrix.sync.aligned.m8n8.x4.shared.b16 {%0,%1,%2,%3}, [%4];" \
        : "=r"(r0), "=r"(r1), "=r"(r2), "=r"(r3) : "r"(addr))

#define MMAF16(d0, d1, d2, d3, a0, a1, a2, a3, b0, b1) \
    asm volatile("mma.sync.aligned.m16n8k16.row.col.f32.f16.f16.f32 " \
        "{%0,%1,%2,%3}, {%4,%5,%6,%7}, {%8,%9}, {%0,%1,%2,%3};" \
        : "+f"(d0), "+f"(d1), "+f"(d2), "+f"(d3) \
        : "r"(a0), "r"(a1), "r"(a2), "r"(a3), "r"(b0), "r"(b1))

// ---------------- scratch ----------------
__device__ float g_qkvp[(size_t)NB*NS*NQKV];
__device__ float g_Q  [(size_t)NB*NH*NS*ND];
__device__ float g_K  [(size_t)NB*NKV*NS*ND];
__device__ float g_V  [(size_t)NB*NKV*NS*ND];
__device__ float g_bs [(size_t)NB*NKV*(NS/64)*ND];
__device__ float g_invf[128];

__device__ __half g_ah[(size_t)NB*NS*NHID], g_al[(size_t)NB*NS*NHID];
__device__ __half g_wqkv[(size_t)NQKV*NHID];
__device__ __half g_wo[(size_t)NHID*NHID];
__device__ __half g_oh[(size_t)NB*NS*NHID];

// ---------------- rope inv-freq table (fp64 once) ----------------
__global__ void invf_init_kernel(float* tab) {
    int j = threadIdx.x;
    tab[j] = (float)exp2(-(double)j * 0.15571537944784511);  // log2(1e6)/128
}

// ---------------- fp32 -> fp16 hi/lo split ----------------
__global__ __launch_bounds__(256) void cvt_split_h(
    const float* __restrict__ x, __half* __restrict__ hi,
    __half* __restrict__ lo, int n4)
{
    int i = blockIdx.x * 256 + threadIdx.x;
    if (i >= n4) return;
    float4 v = *(const float4*)(x + (size_t)i * 4);
    __half h0 = __float2half(v.x), h1 = __float2half(v.y);
    __half h2 = __float2half(v.z), h3 = __float2half(v.w);
    __half l0 = __float2half(v.x - __half2float(h0));
    __half l1 = __float2half(v.y - __half2float(h1));
    __half l2 = __float2half(v.z - __half2float(h2));
    __half l3 = __float2half(v.w - __half2float(h3));
    ushort4 H, L;
    H.x = __half_as_ushort(h0); H.y = __half_as_ushort(h1);
    H.z = __half_as_ushort(h2); H.w = __half_as_ushort(h3);
    L.x = __half_as_ushort(l0); L.y = __half_as_ushort(l1);
    L.z = __half_as_ushort(l2); L.w = __half_as_ushort(l3);
    *(ushort4*)(hi + (size_t)i * 4) = H;
    *(ushort4*)(lo + (size_t)i * 4) = L;
}

// ---------------- fused weight conversion ----------------
__global__ __launch_bounds__(256) void cvt_weights(
    const float* __restrict__ Wq, const float* __restrict__ Wk,
    const float* __restrict__ Wv, const float* __restrict__ Wo,
    __half* __restrict__ wqkv, __half* __restrict__ wo)
{
    int blk = blockIdx.x;
    const float* src; __half* dst; int rel;
    if (blk < 4096)      { src = Wq; dst = wqkv;                        rel = blk; }
    else if (blk < 5120) { src = Wk; dst = wqkv + (size_t)2048 * NHID;  rel = blk - 4096; }
    else if (blk < 6144) { src = Wv; dst = wqkv + (size_t)2560 * NHID;  rel = blk - 5120; }
    else                 { src = Wo; dst = wo;                          rel = blk - 6144; }
    int i = rel * 256 + threadIdx.x;
    float4 v = *(const float4*)(src + (size_t)i * 4);
    ushort4 H;
    H.x = __half_as_ushort(__float2half(v.x));
    H.y = __half_as_ushort(__float2half(v.y));
    H.z = __half_as_ushort(__float2half(v.z));
    H.w = __half_as_ushort(__float2half(v.w));
    *(ushort4*)(dst + (size_t)i * 4) = H;
}

// ================= 2-term split GEMM (Ah*B + Al*B, f32 accum) =================
#define GS_STAGE 49152
#define GS_AH 0
#define GS_AL 16384
#define GS_B  32768
#define GS_TOTAL (2 * GS_STAGE)

__global__ __launch_bounds__(512, 2) void gemm_mma2(
    const __half* __restrict__ Ah, const __half* __restrict__ Al,
    const __half* __restrict__ B,
    float* __restrict__ C, int M, int ldc, int K)
{
    extern __shared__ char sm[];
    u32 sb = smem_u32(sm);
    int tid = threadIdx.x;
    int lane = tid & 31, wid = tid >> 5;
    int warpM = wid & 3, warpN = wid >> 2;
    int bm = blockIdx.y * 128, bn = blockIdx.x * 128;

    const int nIt = K >> 6;

    float d[2][4][4];
#pragma unroll
    for (int i = 0; i < 2; i++)
#pragma unroll
        for (int j = 0; j < 4; j++)
#pragma unroll
            for (int c = 0; c < 4; c++) d[i][j][c] = 0.f;

    int lr = tid >> 3, lcb = tid & 7;
    u32 ldo = SWZ((u32)(lr * 128 + lcb * 16));
    size_t gA = (size_t)(bm + lr) * K + lcb * 8;
    size_t gB = (size_t)(bn + lr) * K + lcb * 8;
    size_t rowK64 = (size_t)64 * K;

#pragma unroll
    for (int pit = 0; pit < 2; pit++) {
        u32 stg = sb + pit * GS_STAGE;
        int k0 = pit << 6;
        CP_ASYNC16(stg + GS_AH + ldo,        Ah + gA + k0);
        CP_ASYNC16(stg + GS_AH + ldo + 8192, Ah + gA + rowK64 + k0);
        CP_ASYNC16(stg + GS_AL + ldo,        Al + gA + k0);
        CP_ASYNC16(stg + GS_AL + ldo + 8192, Al + gA + rowK64 + k0);
        CP_ASYNC16(stg + GS_B  + ldo,        B  + gB + k0);
        CP_ASYNC16(stg + GS_B  + ldo + 8192, B  + gB + rowK64 + k0);
        CP_COMMIT();
    }

    u32 arowb[2], axm[2];
#pragma unroll
    for (int i = 0; i < 2; i++) {
        int row = warpM * 32 + i * 16 + (lane & 15);
        arowb[i] = (u32)(row * 128);
        axm[i] = (u32)((row & 7) << 4);
    }
    u32 browb[2], bxm[2];
#pragma unroll
    for (int p = 0; p < 2; p++) {
        int row = warpN * 32 + p * 16 + (lane & 7) + ((lane >> 4) << 3);
        browb[p] = (u32)(row * 128);
        bxm[p] = (u32)((row & 7) << 4);
    }
    u32 colA_base = (u32)((lane >> 4) << 4);
    u32 colB_base = (u32)(((lane >> 3) & 1) << 4);

    for (int it = 0; it < nIt; it++) {
        CP_WAIT1();
        __syncthreads();
        u32 stgA = sb + (it & 1) * GS_STAGE;
#pragma unroll
        for (int kk = 0; kk < 4; kk++) {
            u32 colA = (u32)(kk * 32) + colA_base;
            u32 colB = (u32)(kk * 32) + colB_base;
            u32 ah[2][4], al[2][4], bb[2][4];
#pragma unroll
            for (int i = 0; i < 2; i++) {
                u32 off = arowb[i] + (colA ^ axm[i]);
                LDMX4(ah[i][0], ah[i][1], ah[i][2], ah[i][3], stgA + GS_AH + off);
                LDMX4(al[i][0], al[i][1], al[i][2], al[i][3], stgA + GS_AL + off);
            }
#pragma unroll
            for (int p = 0; p < 2; p++)
                LDMX4(bb[p][0], bb[p][1], bb[p][2], bb[p][3],
                      stgA + GS_B + browb[p] + (colB ^ bxm[p]));
#pragma unroll
            for (int i = 0; i < 2; i++)
#pragma unroll
                for (int j = 0; j < 4; j++) {
                    int p = j >> 1, h2 = (j & 1) << 1;
                    MMAF16(d[i][j][0], d[i][j][1], d[i][j][2], d[i][j][3],
                           ah[i][0], ah[i][1], ah[i][2], ah[i][3],
                           bb[p][h2], bb[p][h2 + 1]);
                }
#pragma unroll
            for (int i = 0; i < 2; i++)
#pragma unroll
                for (int j = 0; j < 4; j++) {
                    int p = j >> 1, h2 = (j & 1) << 1;
                    MMAF16(d[i][j][0], d[i][j][1], d[i][j][2], d[i][j][3],
                           al[i][0], al[i][1], al[i][2], al[i][3],
                           bb[p][h2], bb[p][h2 + 1]);
                }
        }
        __syncthreads();
        if (it + 2 < nIt) {
            u32 stg = sb + (it & 1) * GS_STAGE;
            int k0 = (it + 2) << 6;
            CP_ASYNC16(stg + GS_AH + ldo,        Ah + gA + k0);
            CP_ASYNC16(stg + GS_AH + ldo + 8192, Ah + gA + rowK64 + k0);
            CP_ASYNC16(stg + GS_AL + ldo,        Al + gA + k0);
            CP_ASYNC16(stg + GS_AL + ldo + 8192, Al + gA + rowK64 + k0);
            CP_ASYNC16(stg + GS_B  + ldo,        B  + gB + k0);
            CP_ASYNC16(stg + GS_B  + ldo + 8192, B  + gB + rowK64 + k0);
        }
        CP_COMMIT();
    }
    CP_WAIT0();

#pragma unroll
    for (int i = 0; i < 2; i++) {
#pragma unroll
        for (int j = 0; j < 4; j++) {
            int r0 = bm + warpM * 32 + i * 16 + (lane >> 2);
            int cc = bn + warpN * 32 + j * 8 + (lane & 3) * 2;
            float2 v0 = make_float2(d[i][j][0], d[i][j][1]);
            float2 v1 = make_float2(d[i][j][2], d[i][j][3]);
            *(float2*)(C + (size_t)r0 * ldc + cc) = v0;
            *(float2*)(C + (size_t)(r0 + 8) * ldc + cc) = v1;
        }
    }
}

// ================= single-term GEMM (A*B, f32 accum) =================
#define G1_STAGE 32768
#define G1_A 0
#define G1_B 16384
#define G1_TOTAL (2 * G1_STAGE)

__global__ __launch_bounds__(512, 2) void gemm_mma1(
    const __half* __restrict__ A, const __half* __restrict__ B,
    float* __restrict__ C, int M, int ldc, int K)
{
    extern __shared__ char sm[];
    u32 sb = smem_u32(sm);
    int tid = threadIdx.x;
    int lane = tid & 31, wid = tid >> 5;
    int warpM = wid & 3, warpN = wid >> 2;
    int bm = blockIdx.y * 128, bn = blockIdx.x * 128;

    const int nIt = K >> 6;

    float d[2][4][4];
#pragma unroll
    for (int i = 0; i < 2; i++)
#pragma unroll
        for (int j = 0; j < 4; j++)
#pragma unroll
            for (int c = 0; c < 4; c++) d[i][j][c] = 0.f;

    int lr = tid >> 3, lcb = tid & 7;
    u32 ldo = SWZ((u32)(lr * 128 + lcb * 16));
    size_t gA = (size_t)(bm + lr) * K + lcb * 8;
    size_t gB = (size_t)(bn + lr) * K + lcb * 8;
    size_t rowK64 = (size_t)64 * K;

#pragma unroll
    for (int pit = 0; pit < 2; pit++) {
        u32 stg = sb + pit * G1_STAGE;
        int k0 = pit << 6;
        CP_ASYNC16(stg + G1_A + ldo,        A + gA + k0);
        CP_ASYNC16(stg + G1_A + ldo + 8192, A + gA + rowK64 + k0);
        CP_ASYNC16(stg + G1_B + ldo,        B + gB + k0);
        CP_ASYNC16(stg + G1_B + ldo + 8192, B + gB + rowK64 + k0);
        CP_COMMIT();
    }

    u32 arowb[2], axm[2];
#pragma unroll
    for (int i = 0; i < 2; i++) {
        int row = warpM * 32 + i * 16 + (lane & 15);
        arowb[i] = (u32)(row * 128);
        axm[i] = (u32)((row & 7) << 4);
    }
    u32 browb[2], bxm[2];
#pragma unroll
    for (int p = 0; p < 2; p++) {
        int row = warpN * 32 + p * 16 + (lane & 7) + ((lane >> 4) << 3);
        browb[p] = (u32)(row * 128);
        bxm[p] = (u32)((row & 7) << 4);
    }
    u32 colA_base = (u32)((lane >> 4) << 4);
    u32 colB_base = (u32)(((lane >> 3) & 1) << 4);

    for (int it = 0; it < nIt; it++) {
        CP_WAIT1();
        __syncthreads();
        u32 stgA = sb + (it & 1) * G1_STAGE;
#pragma unroll
        for (int kk = 0; kk < 4; kk++) {
            u32 colA = (u32)(kk * 32) + colA_base;
            u32 colB = (u32)(kk * 32) + colB_base;
            u32 aa[2][4], bb[2][4];
#pragma unroll
            for (int i = 0; i < 2; i++) {
                u32 off = arowb[i] + (colA ^ axm[i]);
                LDMX4(aa[i][0], aa[i][1], aa[i][2], aa[i][3], stgA + G1_A + off);
            }
#pragma unroll
            for (int p = 0; p < 2; p++)
                LDMX4(bb[p][0], bb[p][1], bb[p][2], bb[p][3],
                      stgA + G1_B + browb[p] + (colB ^ bxm[p]));
#pragma unroll
            for (int i = 0; i < 2; i++)
#pragma unroll
                for (int j = 0; j < 4; j++) {
                    int p = j >> 1, h2 = (j & 1) << 1;
                    MMAF16(d[i][j][0], d[i][j][1], d[i][j][2], d[i][j][3],
                           aa[i][0], aa[i][1], aa[i][2], aa[i][3],
                           bb[p][h2], bb[p][h2 + 1]);
                }
        }
        __syncthreads();
        if (it + 2 < nIt) {
            u32 stg = sb + (it & 1) * G1_STAGE;
            int k0 = (it + 2) << 6;
            CP_ASYNC16(stg + G1_A + ldo,        A + gA + k0);
            CP_ASYNC16(stg + G1_A + ldo + 8192, A + gA + rowK64 + k0);
            CP_ASYNC16(stg + G1_B + ldo,        B + gB + k0);
            CP_ASYNC16(stg + G1_B + ldo + 8192, B + gB + rowK64 + k0);
        }
        CP_COMMIT();
    }
    CP_WAIT0();

#pragma unroll
    for (int i = 0; i < 2; i++) {
#pragma unroll
        for (int j = 0; j < 4; j++) {
            int r0 = bm + warpM * 32 + i * 16 + (lane >> 2);
            int cc = bn + warpN * 32 + j * 8 + (lane & 3) * 2;
            float2 v0 = make_float2(d[i][j][0], d[i][j][1]);
            float2 v1 = make_float2(d[i][j][2], d[i][j][3]);
            *(float2*)(C + (size_t)r0 * ldc + cc) = v0;
            *(float2*)(C + (size_t)(r0 + 8) * ldc + cc) = v1;
        }
    }
}

// ---------------- fused RoPE + unit-LayerNorm (+ q scale) ----------------
__global__ __launch_bounds__(256) void rope_ln_kernel(
    const float* __restrict__ qkvp, const float* __restrict__ invf_tab,
    float* __restrict__ Qo, float* __restrict__ Ko, float* __restrict__ Vo)
{
    __shared__ float sh[ND];
    __shared__ float redA[8], redB[8];
    __shared__ float s_mu, s_inv;
    int bs = blockIdx.x;
    int s  = bs & (NS - 1);
    int b  = bs >> 11;
    int u  = blockIdx.y;
    int d  = threadIdx.x;

    const float* src; float* dst; bool doRope; float scale;
    if (u < NH) {
        src = qkvp + (size_t)bs * NQKV + u * ND;
        dst = Qo + (((size_t)(b * NH + u) * NS) + s) * ND;
        doRope = true; scale = 16.0f;
    } else if (u < NH + NKV) {
        int h = u - NH;
        src = qkvp + (size_t)bs * NQKV + 2048 + h * ND;
        dst = Ko + (((size_t)(b * NKV + h) * NS) + s) * ND;
        doRope = true; scale = 1.0f;
    } else {
        int h = u - NH - NKV;
        src = qkvp + (size_t)bs * NQKV + 2560 + h * ND;
        dst = Vo + (((size_t)(b * NKV + h) * NS) + s) * ND;
        doRope = false; scale = 1.0f;
    }

    float x = src[d];
    float r = x;
    if (doRope) {
        sh[d] = x;
        __syncthreads();
        int j = d & 127;
        float invf = invf_tab[j];
        float ang = (float)s * invf;
        float c = cosf(ang), sn = sinf(ang);
        float partner = (d < 128) ? -sh[d + 128] : sh[d - 128];
        r = x * c + partner * sn;
    }
    float s1 = r, s2 = r * r;
#pragma unroll
    for (int off = 16; off; off >>= 1) {
        s1 += __shfl_xor_sync(~0u, s1, off);
        s2 += __shfl_xor_sync(~0u, s2, off);
    }
    int w = d >> 5;
    if ((d & 31) == 0) { redA[w] = s1; redB[w] = s2; }
    __syncthreads();
    if (d == 0) {
        float A = 0.f, Bv = 0.f;
#pragma unroll
        for (int i = 0; i < 8; i++) { A += redA[i]; Bv += redB[i]; }
        float mu  = A * (1.0f / 256.0f);
        float var = Bv * (1.0f / 256.0f) - mu * mu;
        s_mu = mu; s_inv = rsqrtf(var + 1e-6f);
    }
    __syncthreads();
    dst[d] = (r - s_mu) * s_inv * scale;
}

// ---------------- 64-row block sums of V (mask-correction) ----------------
__global__ __launch_bounds__(256) void vblocksum_kernel(
    const float* __restrict__ V, float* __restrict__ BSo)
{
    int bh = blockIdx.x, blk = blockIdx.y, d = threadIdx.x;
    const float* v = V + ((size_t)bh * NS + blk * 64) * ND + d;
    float s = 0.f;
#pragma unroll 8
    for (int i = 0; i < 64; i++) s += v[(size_t)i * ND];
    BSo[((size_t)bh * (NS / 64) + blk) * ND + d] = s;
}

// ---------------- sliding-window softcapped flash attention ----------------
// PV: interleaved V-column ownership {4tx + 64g} (2-wavefront LDS.128)
// QK: Kt XOR-swizzled [d][ (row>>2)^( (d>>2)&15 ) ][row&3], stride 64
//     -> stores 2-way instead of 16-way; loads stay conflict-free
#define AT_BM 64
#define AT_BN 64
#define QS_STR 260
#define VS_STR 260
#define PS_STR 68
// layout (floats): Qs 16640 | Kt 16384 | Vs 16640 | Ps 4352 | corrv 256
#define ATT_SMEM ((16640 + 16384 + 16640 + 4352 + 256) * 4)

__global__ __launch_bounds__(256, 1) void attn_kernel(
    const float* __restrict__ Q, const float* __restrict__ K,
    const float* __restrict__ V, const float* __restrict__ BS,
    __half* __restrict__ OH)
{
    extern __shared__ __align__(16) float smf[];
    float* Qs    = smf;
    float* Kt    = smf + 16640;
    float* Vs    = smf + 33024;
    float* Ps    = smf + 49664;
    float* corrv = smf + 54016;

    int tid = threadIdx.x;
    int tx = tid & 15, ty = tid >> 4;
    int qt = blockIdx.x, h = blockIdx.y, b = blockIdx.z;
    int qs = qt * AT_BM;
    int kvh = h >> 2;

    const float* Qb = Q + (((size_t)(b * NH  + h  ) * NS) + qs) * ND;
    const float* Kb = K + ((size_t)(b * NKV + kvh) * NS) * ND;
    const float* Vb = V + ((size_t)(b * NKV + kvh) * NS) * ND;
    const float* Bb = BS + (size_t)(b * NKV + kvh) * (NS / 64) * ND;

    int t0 = qs - (NSW - 1);
    int kstart = (t0 <= 0) ? 0 : (t0 & ~63);
    int kend = qs + AT_BM;
    float Ncf = (float)(NS - (kend - kstart));
    int bs0 = kstart >> 6, bs1 = kend >> 6;

    {
        float c = 0.f;
#pragma unroll
        for (int blk = 0; blk < NS / 64; blk++) {
            float x = Bb[(size_t)blk * ND + tid];
            if (blk < bs0 || blk >= bs1) c += x;
        }
        corrv[tid] = c;
    }
#pragma unroll
    for (int it = 0; it < 16; it++) {
        int idx = tid + it * 256;
        int row = idx >> 6, c4 = idx & 63;
        float4 qv = *(const float4*)(Qb + (size_t)row * ND + (c4 << 2));
        float* q = Qs + row * QS_STR + (c4 << 2);
        q[0] = qv.x; q[1] = qv.y; q[2] = qv.z; q[3] = qv.w;
    }

    float2 acc[4][8];
#pragma unroll
    for (int i = 0; i < 4; i++)
#pragma unroll
        for (int c = 0; c < 8; c++) acc[i][c] = make_float2(0.f, 0.f);
    float Mrow[4], Lrow[4];
#pragma unroll
    for (int i = 0; i < 4; i++) { Mrow[i] = -3.0e38f; Lrow[i] = 0.f; }

    for (int k0 = kstart; k0 < kend; k0 += AT_BN) {
        __syncthreads();
#pragma unroll
        for (int it = 0; it < 16; it++) {
            int idx = tid + it * 256;
            int row = idx >> 6, c4 = idx & 63;
            float4 kv = *(const float4*)(Kb + (size_t)(k0 + row) * ND + (c4 << 2));
            // XOR-swizzled transpose: d = 4*c4 + j
            u32 kb = (u32)((c4 << 8) + ((((row >> 2) ^ (c4 & 15)) << 2) | (row & 3)));
            Kt[kb      ] = kv.x;
            Kt[kb +  64] = kv.y;
            Kt[kb + 128] = kv.z;
            Kt[kb + 192] = kv.w;
            float4 vv = *(const float4*)(Vb + (size_t)(k0 + row) * ND + (c4 << 2));
            *(float4*)(Vs + row * VS_STR + (c4 << 2)) = vv;
        }
        __syncthreads();

        float2 s2[4][2];
#pragma unroll
        for (int i = 0; i < 4; i++) { s2[i][0] = make_float2(0.f,0.f); s2[i][1] = make_float2(0.f,0.f); }
        const float* qrow = Qs + (ty << 2) * QS_STR;
#pragma unroll 8
        for (int d = 0; d < ND; d++) {
            float4 kq = *(const float4*)(Kt + (d << 6) + ((tx ^ ((d >> 2) & 15)) << 2));
            float2 b01 = make_float2(kq.x, kq.y);
            float2 b23 = make_float2(kq.z, kq.w);
#pragma unroll
            for (int ii = 0; ii < 4; ii++) {
                float a = qrow[ii * QS_STR + d];
                float2 ap = make_float2(a, a);
                s2[ii][0] = ffma2(s2[ii][0], ap, b01);
                s2[ii][1] = ffma2(s2[ii][1], ap, b23);
            }
        }

#pragma unroll
        for (int ii = 0; ii < 4; ii++) {
            int gi = qs + (ty << 2) + ii;
            float sc[4] = { s2[ii][0].x, s2[ii][0].y, s2[ii][1].x, s2[ii][1].y };
            float rmax = -1e30f;
#pragma unroll
            for (int jj = 0; jj < 4; jj++) {
                int gj = k0 + (tx << 2) + jj;
                float v;
                if (gj <= gi && gj > gi - NSW)
                    v = 30.0f * tanhf(sc[jj] * (1.0f / 30.0f));
                else
                    v = -30.0f;
                sc[jj] = v;
                rmax = fmaxf(rmax, v);
            }
#pragma unroll
            for (int off = 8; off; off >>= 1) rmax = fmaxf(rmax, __shfl_xor_sync(~0u, rmax, off));
            float Mnew = fmaxf(Mrow[ii], rmax);
            float f = expf(Mrow[ii] - Mnew);
            Mrow[ii] = Mnew;
            float rs = 0.f;
#pragma unroll
            for (int jj = 0; jj < 4; jj++) {
                float p = expf(sc[jj] - Mnew);
                Ps[((ty << 2) + ii) * PS_STR + (tx << 2) + jj] = p;
                rs += p;
            }
#pragma unroll
            for (int off = 8; off; off >>= 1) rs += __shfl_xor_sync(~0u, rs, off);
            Lrow[ii] = Lrow[ii] * f + rs;
#pragma unroll
            for (int cc = 0; cc < 8; cc++) { acc[ii][cc].x *= f; acc[ii][cc].y *= f; }
        }
        __syncthreads();

        // PV with interleaved column ownership: cols {4tx + 64g}
#pragma unroll 4
        for (int kk = 0; kk < AT_BN; kk++) {
            const float* vrow = Vs + kk * VS_STR + (tx << 2);
            float4 v0 = *(const float4*)(vrow);
            float4 v1 = *(const float4*)(vrow + 64);
            float4 v2 = *(const float4*)(vrow + 128);
            float4 v3 = *(const float4*)(vrow + 192);
            float2 vv[8] = {
                make_float2(v0.x,v0.y), make_float2(v0.z,v0.w),
                make_float2(v1.x,v1.y), make_float2(v1.z,v1.w),
                make_float2(v2.x,v2.y), make_float2(v2.z,v2.w),
                make_float2(v3.x,v3.y), make_float2(v3.z,v3.w)
            };
#pragma unroll
            for (int ii = 0; ii < 4; ii++) {
                float p = Ps[((ty << 2) + ii) * PS_STR + kk];
                float2 pp = make_float2(p, p);
#pragma unroll
                for (int cc = 0; cc < 8; cc++) acc[ii][cc] = ffma2(acc[ii][cc], pp, vv[cc]);
            }
        }
    }

    // epilogue: exact masked correction, normalize, write fp16 (interleaved cols)
#pragma unroll
    for (int ii = 0; ii < 4; ii++) {
        float ce = expf(-30.0f - Mrow[ii]);
        float invL = 1.0f / (Lrow[ii] + ce * Ncf);
        int row = qs + (ty << 2) + ii;
        size_t obase = ((size_t)(b * NS + row) * NHID) + h * ND;
#pragma unroll
        for (int g = 0; g < 4; g++) {
            float2 a0 = acc[ii][g * 2], a1 = acc[ii][g * 2 + 1];
            int c0 = (tx << 2) + g * 64;
            float o0 = (a0.x + ce * corrv[c0 + 0]) * invL;
            float o1 = (a0.y + ce * corrv[c0 + 1]) * invL;
            float o2 = (a1.x + ce * corrv[c0 + 2]) * invL;
            float o3 = (a1.y + ce * corrv[c0 + 3]) * invL;
            ushort4 H;
            H.x = __half_as_ushort(__float2half(o0));
            H.y = __half_as_ushort(__float2half(o1));
            H.z = __half_as_ushort(__float2half(o2));
            H.w = __half_as_ushort(__float2half(o3));
            *(ushort4*)(OH + obase + c0) = H;
        }
    }
}

// ---------------- launch ----------------
extern "C" void kernel_launch(void* const* d_in, const int* in_sizes, int n_in,
                              void* d_out, int out_size)
{
    const float* hs = (const float*)d_in[0];
    const float* Wq = (const float*)d_in[1];
    const float* Wk = (const float*)d_in[2];
    const float* Wv = (const float*)d_in[3];
    const float* Wo = (const float*)d_in[4];
    float* out = (float*)d_out;

    float *qkvp, *Qn, *Kn, *Vn, *bs, *invf;
    cudaGetSymbolAddress((void**)&qkvp, g_qkvp);
    cudaGetSymbolAddress((void**)&Qn,  g_Q);
    cudaGetSymbolAddress((void**)&Kn,  g_K);
    cudaGetSymbolAddress((void**)&Vn,  g_V);
    cudaGetSymbolAddress((void**)&bs,  g_bs);
    cudaGetSymbolAddress((void**)&invf, g_invf);

    __half *ah,*al,*wqkv,*wo,*oh;
    cudaGetSymbolAddress((void**)&ah, g_ah); cudaGetSymbolAddress((void**)&al, g_al);
    cudaGetSymbolAddress((void**)&wqkv, g_wqkv);
    cudaGetSymbolAddress((void**)&wo, g_wo);
    cudaGetSymbolAddress((void**)&oh, g_oh);

    const int M = NB * NS;   // 4096

    cudaFuncSetAttribute(gemm_mma2, cudaFuncAttributeMaxDynamicSharedMemorySize, GS_TOTAL);
    cudaFuncSetAttribute(gemm_mma1, cudaFuncAttributeMaxDynamicSharedMemorySize, G1_TOTAL);
    cudaFuncSetAttribute(attn_kernel, cudaFuncAttributeMaxDynamicSharedMemorySize, ATT_SMEM);

    // rope inv-freq table
    invf_init_kernel<<<1, 128>>>(invf);

    // conversions
    cvt_split_h<<<(M * NHID) / 1024, 256>>>(hs, ah, al, (M * NHID) / 4);
    cvt_weights<<<10240, 256>>>(Wq, Wk, Wv, Wo, wqkv, wo);

    // Q projection: single-term fp16
    gemm_mma1<<<dim3(2048/128, M/128), 512, G1_TOTAL>>>(ah, wqkv, qkvp, M, NQKV, NHID);
    // K/V projections: 2-term split
    gemm_mma2<<<dim3(1024/128, M/128), 512, GS_TOTAL>>>(ah, al, wqkv + (size_t)2048*NHID,
                                                        qkvp + 2048, M, NQKV, NHID);

    // rope + per-head layernorm (+ query scaling folded)
    rope_ln_kernel<<<dim3(NB * NS, NH + 2 * NKV), 256>>>(qkvp, invf, Qn, Kn, Vn);

    // 64-row block sums of normalized V
    vblocksum_kernel<<<dim3(NB * NKV, NS / 64), 256>>>(Vn, bs);

    // attention (conflict-free PV + swizzled Kt)
    attn_kernel<<<dim3(NS / AT_BM, NH, NB), 256, ATT_SMEM>>>(Qn, Kn, Vn, bs, oh);

    // output projection: single-term fp16
    gemm_mma1<<<dim3(NHID/128, M/128), 512, G1_TOTAL>>>(oh, wo, out, M, NHID, NHID);
}